// round 1
// baseline (speedup 1.0000x reference)
#include <cuda_runtime.h>
#include <math.h>

// Problem constants
#define BB 4
#define TT 2048
#define CC 768
#define HH 12
#define DD 64
#define NROWS (BB*TT)          // 8192
#define QKVC (3*CC)            // 2304
#define FFC (4*CC)             // 3072

// ---------------- scratch (allocation-free: __device__ globals) ----------------
__device__ float g_h1 [NROWS*CC];    // ln1(x)
__device__ float g_qkv[NROWS*QKVC];  // qkv
__device__ float g_y  [NROWS*CC];    // attention out
__device__ float g_x1 [NROWS*CC];    // x + aproj
__device__ float g_h2 [NROWS*CC];    // ln2(x1)
__device__ float g_fc [NROWS*FFC];   // gelu(fc)

// ---------------- LayerNorm: one warp per row ----------------
__global__ __launch_bounds__(256) void ln_kernel(const float* __restrict__ x,
                                                 const float* __restrict__ g,
                                                 const float* __restrict__ bt,
                                                 float* __restrict__ out)
{
    const int row  = blockIdx.x * 8 + (threadIdx.x >> 5);
    const int lane = threadIdx.x & 31;
    const float* xr = x + (size_t)row * CC;

    float4 v[6];
    float sum = 0.f;
    #pragma unroll
    for (int i = 0; i < 6; ++i) {
        v[i] = *(const float4*)(xr + lane*4 + i*128);
        sum += (v[i].x + v[i].y) + (v[i].z + v[i].w);
    }
    #pragma unroll
    for (int off = 16; off > 0; off >>= 1) sum += __shfl_xor_sync(0xffffffffu, sum, off);
    const float mu = sum * (1.0f/768.0f);

    float var = 0.f;
    #pragma unroll
    for (int i = 0; i < 6; ++i) {
        float dx;
        dx = v[i].x - mu; var += dx*dx;
        dx = v[i].y - mu; var += dx*dx;
        dx = v[i].z - mu; var += dx*dx;
        dx = v[i].w - mu; var += dx*dx;
    }
    #pragma unroll
    for (int off = 16; off > 0; off >>= 1) var += __shfl_xor_sync(0xffffffffu, var, off);
    const float rstd = rsqrtf(var * (1.0f/768.0f) + 1e-5f);

    float* orow = out + (size_t)row * CC;
    #pragma unroll
    for (int i = 0; i < 6; ++i) {
        const int col = lane*4 + i*128;
        const float4 gg = *(const float4*)(g  + col);
        const float4 bb = *(const float4*)(bt + col);
        float4 r;
        r.x = (v[i].x - mu)*rstd*gg.x + bb.x;
        r.y = (v[i].y - mu)*rstd*gg.y + bb.y;
        r.z = (v[i].z - mu)*rstd*gg.z + bb.z;
        r.w = (v[i].w - mu)*rstd*gg.w + bb.w;
        *(float4*)(orow + col) = r;
    }
}

// ---------------- GELU (tanh approximation, exact match to jax approximate) ----------------
__device__ __forceinline__ float gelu_tanh(float v) {
    const float c = 0.7978845608028654f;
    float u = c * (v + 0.044715f * v * v * v);
    return 0.5f * v * (1.0f + tanhf(u));
}

// ---------------- fp32 GEMM: C[M,N] = A[M,K] @ B[K,N] + bias (+epilogue) ----------------
// BM=BN=128, BK=8, 256 threads, 8x8 microtile, double-buffered shared.
// EPI: 0 = bias, 1 = bias+gelu, 2 = bias+residual
template<int EPI>
__global__ __launch_bounds__(256) void gemm_kernel(
    const float* __restrict__ A, const float* __restrict__ B,
    const float* __restrict__ bias, const float* __restrict__ res,
    float* __restrict__ C, int M, int N, int K)
{
    __shared__ float As[2][8][128];   // A transposed: As[k][m]
    __shared__ float Bs[2][8][128];

    const int t  = threadIdx.x;
    const int tx = t & 15, ty = t >> 4;
    const int m0 = blockIdx.y * 128, n0 = blockIdx.x * 128;

    const int aRow = t >> 1;
    const int aK   = (t & 1) * 4;
    const int bK   = t >> 5;
    const int bCol = (t & 31) * 4;
    const float* Ag = A + (size_t)(m0 + aRow) * K + aK;
    const float* Bg = B + (size_t)bK * N + n0 + bCol;

    float acc[8][8];
    #pragma unroll
    for (int i = 0; i < 8; ++i)
        #pragma unroll
        for (int j = 0; j < 8; ++j) acc[i][j] = 0.f;

    float4 a4 = *(const float4*)Ag;
    float4 b4 = *(const float4*)Bg;
    As[0][aK+0][aRow] = a4.x; As[0][aK+1][aRow] = a4.y;
    As[0][aK+2][aRow] = a4.z; As[0][aK+3][aRow] = a4.w;
    *(float4*)&Bs[0][bK][bCol] = b4;
    __syncthreads();

    const int ntiles = K >> 3;
    for (int tile = 0; tile < ntiles; ++tile) {
        const int cur = tile & 1;
        if (tile + 1 < ntiles) {
            a4 = *(const float4*)(Ag + (tile + 1) * 8);
            b4 = *(const float4*)(Bg + (size_t)(tile + 1) * 8 * N);
        }
        #pragma unroll
        for (int kk = 0; kk < 8; ++kk) {
            const float4 af0 = *(const float4*)&As[cur][kk][ty*8];
            const float4 af1 = *(const float4*)&As[cur][kk][ty*8+4];
            const float4 bf0 = *(const float4*)&Bs[cur][kk][tx*8];
            const float4 bf1 = *(const float4*)&Bs[cur][kk][tx*8+4];
            const float a[8]  = {af0.x,af0.y,af0.z,af0.w,af1.x,af1.y,af1.z,af1.w};
            const float bb[8] = {bf0.x,bf0.y,bf0.z,bf0.w,bf1.x,bf1.y,bf1.z,bf1.w};
            #pragma unroll
            for (int i = 0; i < 8; ++i)
                #pragma unroll
                for (int j = 0; j < 8; ++j)
                    acc[i][j] = fmaf(a[i], bb[j], acc[i][j]);
        }
        if (tile + 1 < ntiles) {
            const int nxt = cur ^ 1;
            As[nxt][aK+0][aRow] = a4.x; As[nxt][aK+1][aRow] = a4.y;
            As[nxt][aK+2][aRow] = a4.z; As[nxt][aK+3][aRow] = a4.w;
            *(float4*)&Bs[nxt][bK][bCol] = b4;
        }
        __syncthreads();
    }

    #pragma unroll
    for (int i = 0; i < 8; ++i) {
        const size_t row = (size_t)(m0 + ty*8 + i);
        float* crow = C + row * N + n0 + tx*8;
        float v[8];
        if (EPI == 2) {
            const float* rrow = res + row * N + n0 + tx*8;
            const float4 r0 = *(const float4*)(rrow);
            const float4 r1 = *(const float4*)(rrow + 4);
            const float rr[8] = {r0.x,r0.y,r0.z,r0.w,r1.x,r1.y,r1.z,r1.w};
            #pragma unroll
            for (int j = 0; j < 8; ++j)
                v[j] = acc[i][j] + bias[n0 + tx*8 + j] + rr[j];
        } else {
            #pragma unroll
            for (int j = 0; j < 8; ++j) {
                float xv = acc[i][j] + bias[n0 + tx*8 + j];
                if (EPI == 1) xv = gelu_tanh(xv);
                v[j] = xv;
            }
        }
        *(float4*)(crow)     = make_float4(v[0],v[1],v[2],v[3]);
        *(float4*)(crow + 4) = make_float4(v[4],v[5],v[6],v[7]);
    }
}

// ---------------- causal flash attention, fp32, 64x64 tiles ----------------
// grid: (T/64, B*H), 256 threads (16x16), each thread owns 4 q-rows x 4 cols.
__global__ __launch_bounds__(256) void attn_kernel(const float* __restrict__ qkv,
                                                   float* __restrict__ y)
{
    __shared__ float Qs [64*64];   // Q scaled by 1/sqrt(D)
    __shared__ float KPs[64*64];   // K^T during S; reused for P
    __shared__ float Vs [64*64];

    const int t  = threadIdx.x;
    const int tx = t & 15;
    const int ty = t >> 4;
    const int qtile = blockIdx.x;
    const int bh = blockIdx.y;
    const int b  = bh / HH;
    const int h  = bh - b * HH;
    const int qbase = qtile * 64;
    const size_t base = (size_t)b * TT * QKVC + (size_t)h * DD;

    // Load Q tile (scaled)
    {
        const int r  = t >> 2;
        const int d0 = (t & 3) * 16;
        const float* qrow = qkv + base + (size_t)(qbase + r) * QKVC + d0;
        #pragma unroll
        for (int e = 0; e < 16; e += 4) {
            float4 v = *(const float4*)(qrow + e);
            v.x *= 0.125f; v.y *= 0.125f; v.z *= 0.125f; v.w *= 0.125f;
            *(float4*)&Qs[r * 64 + d0 + e] = v;
        }
    }

    float m[4], l[4], o[4][4];
    #pragma unroll
    for (int i = 0; i < 4; ++i) {
        m[i] = -1e30f; l[i] = 0.f;
        #pragma unroll
        for (int j = 0; j < 4; ++j) o[i][j] = 0.f;
    }

    for (int kt = 0; kt <= qtile; ++kt) {
        __syncthreads();   // prev iteration done with KPs/Vs; Q visible on first pass after next sync
        // Load K^T and V tiles
        {
            const int r  = t >> 2;
            const int d0 = (t & 3) * 16;
            const float* krow = qkv + base + CC   + (size_t)(kt*64 + r) * QKVC + d0;
            const float* vrow = qkv + base + 2*CC + (size_t)(kt*64 + r) * QKVC + d0;
            #pragma unroll
            for (int e = 0; e < 16; e += 4) {
                const float4 kv = *(const float4*)(krow + e);
                KPs[(d0+e+0)*64 + r] = kv.x;
                KPs[(d0+e+1)*64 + r] = kv.y;
                KPs[(d0+e+2)*64 + r] = kv.z;
                KPs[(d0+e+3)*64 + r] = kv.w;
                *(float4*)&Vs[r*64 + d0 + e] = *(const float4*)(vrow + e);
            }
        }
        __syncthreads();

        // S = Q @ K^T
        float s[4][4];
        #pragma unroll
        for (int i = 0; i < 4; ++i)
            #pragma unroll
            for (int j = 0; j < 4; ++j) s[i][j] = 0.f;

        #pragma unroll 8
        for (int kk = 0; kk < 64; ++kk) {
            const float4 bb = *(const float4*)&KPs[kk*64 + tx*4];
            #pragma unroll
            for (int i = 0; i < 4; ++i) {
                const float a = Qs[(ty*4+i)*64 + kk];
                s[i][0] = fmaf(a, bb.x, s[i][0]);
                s[i][1] = fmaf(a, bb.y, s[i][1]);
                s[i][2] = fmaf(a, bb.z, s[i][2]);
                s[i][3] = fmaf(a, bb.w, s[i][3]);
            }
        }

        // Causal mask on diagonal tile
        if (kt == qtile) {
            #pragma unroll
            for (int i = 0; i < 4; ++i)
                #pragma unroll
                for (int j = 0; j < 4; ++j)
                    if (tx*4 + j > ty*4 + i) s[i][j] = -1e30f;
        }

        __syncthreads();   // everyone done reading K^T before P overwrites KPs

        // Online softmax stats (reduce across 16 lanes sharing a q-row group)
        #pragma unroll
        for (int i = 0; i < 4; ++i) {
            float tm = fmaxf(fmaxf(s[i][0], s[i][1]), fmaxf(s[i][2], s[i][3]));
            #pragma unroll
            for (int off = 8; off > 0; off >>= 1)
                tm = fmaxf(tm, __shfl_xor_sync(0xffffffffu, tm, off));
            const float mn = fmaxf(m[i], tm);
            const float alpha = __expf(m[i] - mn);
            float rs = 0.f;
            #pragma unroll
            for (int j = 0; j < 4; ++j) {
                const float p = __expf(s[i][j] - mn);
                s[i][j] = p;
                rs += p;
            }
            #pragma unroll
            for (int off = 8; off > 0; off >>= 1)
                rs += __shfl_xor_sync(0xffffffffu, rs, off);
            l[i] = l[i] * alpha + rs;
            m[i] = mn;
            #pragma unroll
            for (int j = 0; j < 4; ++j) o[i][j] *= alpha;
            *(float4*)&KPs[(ty*4+i)*64 + tx*4] = make_float4(s[i][0], s[i][1], s[i][2], s[i][3]);
        }
        __syncthreads();

        // O += P @ V
        #pragma unroll 8
        for (int kk = 0; kk < 64; ++kk) {
            const float4 vv = *(const float4*)&Vs[kk*64 + tx*4];
            #pragma unroll
            for (int i = 0; i < 4; ++i) {
                const float p = KPs[(ty*4+i)*64 + kk];
                o[i][0] = fmaf(p, vv.x, o[i][0]);
                o[i][1] = fmaf(p, vv.y, o[i][1]);
                o[i][2] = fmaf(p, vv.z, o[i][2]);
                o[i][3] = fmaf(p, vv.w, o[i][3]);
            }
        }
    }

    // Normalize and write y[b, q, h*64 + d]
    #pragma unroll
    for (int i = 0; i < 4; ++i) {
        const float inv = 1.0f / l[i];
        const size_t row = (size_t)b * TT + qbase + ty*4 + i;
        *(float4*)&y[row * CC + h*DD + tx*4] =
            make_float4(o[i][0]*inv, o[i][1]*inv, o[i][2]*inv, o[i][3]*inv);
    }
}

// ---------------- launch ----------------
extern "C" void kernel_launch(void* const* d_in, const int* in_sizes, int n_in,
                              void* d_out, int out_size)
{
    const float* x       = (const float*)d_in[0];
    const float* ln1_g   = (const float*)d_in[1];
    const float* ln1_b   = (const float*)d_in[2];
    const float* w_attn  = (const float*)d_in[3];
    const float* b_attn  = (const float*)d_in[4];
    const float* w_aproj = (const float*)d_in[5];
    const float* b_aproj = (const float*)d_in[6];
    const float* ln2_g   = (const float*)d_in[7];
    const float* ln2_b   = (const float*)d_in[8];
    const float* w_fc    = (const float*)d_in[9];
    const float* b_fc    = (const float*)d_in[10];
    const float* w_mproj = (const float*)d_in[11];
    const float* b_mproj = (const float*)d_in[12];
    float* out = (float*)d_out;

    float *h1, *qkv, *y, *x1, *h2, *fc;
    cudaGetSymbolAddress((void**)&h1,  g_h1);
    cudaGetSymbolAddress((void**)&qkv, g_qkv);
    cudaGetSymbolAddress((void**)&y,   g_y);
    cudaGetSymbolAddress((void**)&x1,  g_x1);
    cudaGetSymbolAddress((void**)&h2,  g_h2);
    cudaGetSymbolAddress((void**)&fc,  g_fc);

    // 1) h1 = ln1(x)
    ln_kernel<<<NROWS/8, 256>>>(x, ln1_g, ln1_b, h1);
    // 2) qkv = h1 @ w_attn + b_attn
    gemm_kernel<0><<<dim3(QKVC/128, NROWS/128), 256>>>(h1, w_attn, b_attn, nullptr, qkv, NROWS, QKVC, CC);
    // 3) y = attention(qkv)
    attn_kernel<<<dim3(TT/64, BB*HH), 256>>>(qkv, y);
    // 4) x1 = y @ w_aproj + b_aproj + x
    gemm_kernel<2><<<dim3(CC/128, NROWS/128), 256>>>(y, w_aproj, b_aproj, x, x1, NROWS, CC, CC);
    // 5) h2 = ln2(x1)
    ln_kernel<<<NROWS/8, 256>>>(x1, ln2_g, ln2_b, h2);
    // 6) fc = gelu(h2 @ w_fc + b_fc)
    gemm_kernel<1><<<dim3(FFC/128, NROWS/128), 256>>>(h2, w_fc, b_fc, nullptr, fc, NROWS, FFC, CC);
    // 7) out = fc @ w_mproj + b_mproj + x1
    gemm_kernel<2><<<dim3(CC/128, NROWS/128), 256>>>(fc, w_mproj, b_mproj, x1, out, NROWS, CC, FFC);
}

// round 3
// speedup vs baseline: 1.8136x; 1.8136x over previous
#include <cuda_runtime.h>
#include <cuda_bf16.h>
#include <math.h>
#include <stdint.h>

// Problem constants
#define BB 4
#define TT 2048
#define CC 768
#define HH 12
#define DD 64
#define NROWS (BB*TT)          // 8192
#define QKVC (3*CC)            // 2304
#define FFC (4*CC)             // 3072

// ================= scratch (allocation-free: __device__ globals) =================
__device__ __nv_bfloat16 g_h1h[NROWS*CC],  g_h1l[NROWS*CC];
__device__ float         g_qkv[NROWS*QKVC];
__device__ __nv_bfloat16 g_yh [NROWS*CC],  g_yl [NROWS*CC];
__device__ float         g_x1 [NROWS*CC];
__device__ __nv_bfloat16 g_h2h[NROWS*CC],  g_h2l[NROWS*CC];
__device__ __nv_bfloat16 g_fch[NROWS*FFC], g_fcl[NROWS*FFC];
__device__ __nv_bfloat16 g_wqh[QKVC*CC], g_wql[QKVC*CC];   // [N][K] K-major
__device__ __nv_bfloat16 g_wah[CC*CC],   g_wal[CC*CC];
__device__ __nv_bfloat16 g_wfh[FFC*CC],  g_wfl[FFC*CC];
__device__ __nv_bfloat16 g_wmh[CC*FFC],  g_wml[CC*FFC];

__device__ __forceinline__ void split2(float v, __nv_bfloat16& h, __nv_bfloat16& l) {
    h = __float2bfloat16(v);
    l = __float2bfloat16(v - __bfloat162float(h));
}
__device__ __forceinline__ uint32_t packbf2(__nv_bfloat16 a, __nv_bfloat16 b) {
    return (uint32_t)__bfloat16_as_ushort(a) | ((uint32_t)__bfloat16_as_ushort(b) << 16);
}
__device__ __forceinline__ uint32_t smem_u32(const void* p) {
    uint32_t a;
    asm("{ .reg .u64 t; cvta.to.shared.u64 t, %1; cvt.u32.u64 %0, t; }" : "=r"(a) : "l"(p));
    return a;
}
__device__ __forceinline__ void cp16(uint32_t saddr, const void* g) {
    asm volatile("cp.async.cg.shared.global [%0], [%1], 16;" :: "r"(saddr), "l"(g));
}
#define CP_COMMIT() asm volatile("cp.async.commit_group;" ::: "memory")
#define CP_WAIT1()  asm volatile("cp.async.wait_group 1;" ::: "memory")

__device__ __forceinline__ void ldm_x4(uint32_t* r, uint32_t addr) {
    asm volatile("ldmatrix.sync.aligned.m8n8.x4.shared.b16 {%0,%1,%2,%3}, [%4];"
        : "=r"(r[0]), "=r"(r[1]), "=r"(r[2]), "=r"(r[3]) : "r"(addr));
}
__device__ __forceinline__ void ldm_x2(uint32_t* r, uint32_t addr) {
    asm volatile("ldmatrix.sync.aligned.m8n8.x2.shared.b16 {%0,%1}, [%2];"
        : "=r"(r[0]), "=r"(r[1]) : "r"(addr));
}
__device__ __forceinline__ void mma_bf16(float* c, const uint32_t* a, const uint32_t* b) {
    asm volatile("mma.sync.aligned.m16n8k16.row.col.f32.bf16.bf16.f32 "
        "{%0,%1,%2,%3}, {%4,%5,%6,%7}, {%8,%9}, {%0,%1,%2,%3};"
        : "+f"(c[0]), "+f"(c[1]), "+f"(c[2]), "+f"(c[3])
        : "r"(a[0]), "r"(a[1]), "r"(a[2]), "r"(a[3]), "r"(b[0]), "r"(b[1]));
}

__device__ __forceinline__ float gelu_tanh(float v) {
    const float c = 0.7978845608028654f;
    float u = c * (v + 0.044715f * v * v * v);
    return 0.5f * v * (1.0f + tanhf(u));
}

// ================= weight transpose + split: w[K,N] -> wt_hi/lo[N,K] =================
__global__ __launch_bounds__(256) void tsplit_kernel(const float* __restrict__ w,
                                                     __nv_bfloat16* __restrict__ th,
                                                     __nv_bfloat16* __restrict__ tl,
                                                     int K, int N)
{
    __shared__ float tile[32][33];
    const int tx = threadIdx.x & 31, ty = threadIdx.x >> 5;   // 32x8
    const int n0 = blockIdx.x * 32, k0 = blockIdx.y * 32;
    #pragma unroll
    for (int r = 0; r < 4; ++r)
        tile[ty + 8*r][tx] = w[(size_t)(k0 + ty + 8*r) * N + n0 + tx];
    __syncthreads();
    #pragma unroll
    for (int r = 0; r < 4; ++r) {
        const float v = tile[tx][ty + 8*r];      // w[k0+tx][n0+ty+8r]
        __nv_bfloat16 h, l; split2(v, h, l);
        const size_t o = (size_t)(n0 + ty + 8*r) * K + k0 + tx;
        th[o] = h; tl[o] = l;
    }
}

// ================= LayerNorm -> bf16 split =================
__global__ __launch_bounds__(256) void ln_split_kernel(const float* __restrict__ x,
                                                       const float* __restrict__ g,
                                                       const float* __restrict__ bt,
                                                       __nv_bfloat16* __restrict__ oh,
                                                       __nv_bfloat16* __restrict__ ol)
{
    const int row  = blockIdx.x * 8 + (threadIdx.x >> 5);
    const int lane = threadIdx.x & 31;
    const float* xr = x + (size_t)row * CC;

    float4 v[6];
    float sum = 0.f;
    #pragma unroll
    for (int i = 0; i < 6; ++i) {
        v[i] = *(const float4*)(xr + lane*4 + i*128);
        sum += (v[i].x + v[i].y) + (v[i].z + v[i].w);
    }
    #pragma unroll
    for (int off = 16; off > 0; off >>= 1) sum += __shfl_xor_sync(0xffffffffu, sum, off);
    const float mu = sum * (1.0f/768.0f);
    float var = 0.f;
    #pragma unroll
    for (int i = 0; i < 6; ++i) {
        float dx;
        dx = v[i].x - mu; var += dx*dx;  dx = v[i].y - mu; var += dx*dx;
        dx = v[i].z - mu; var += dx*dx;  dx = v[i].w - mu; var += dx*dx;
    }
    #pragma unroll
    for (int off = 16; off > 0; off >>= 1) var += __shfl_xor_sync(0xffffffffu, var, off);
    const float rstd = rsqrtf(var * (1.0f/768.0f) + 1e-5f);

    #pragma unroll
    for (int i = 0; i < 6; ++i) {
        const int col = lane*4 + i*128;
        const float4 gg = *(const float4*)(g  + col);
        const float4 bb = *(const float4*)(bt + col);
        float r0 = (v[i].x - mu)*rstd*gg.x + bb.x;
        float r1 = (v[i].y - mu)*rstd*gg.y + bb.y;
        float r2 = (v[i].z - mu)*rstd*gg.z + bb.z;
        float r3 = (v[i].w - mu)*rstd*gg.w + bb.w;
        __nv_bfloat16 h0,l0,h1,l1,h2,l2,h3,l3;
        split2(r0,h0,l0); split2(r1,h1,l1); split2(r2,h2,l2); split2(r3,h3,l3);
        const size_t o = (size_t)row * CC + col;
        *(uint2*)(oh + o) = make_uint2(packbf2(h0,h1), packbf2(h2,h3));
        *(uint2*)(ol + o) = make_uint2(packbf2(l0,l1), packbf2(l2,l3));
    }
}

// ================= split-bf16 HMMA GEMM =================
// D[M,N] = (Ah+Al)[M,K] @ (Bh+Bl)^T (B stored [N][K] K-major) + bias [+ res | gelu->split]
// BM=BN=128, BK=64, double-buffered cp.async, 8 warps (2x4), warp tile 64x32.
// EPI: 0 = bias -> fp32; 1 = bias+gelu -> bf16 hi/lo; 2 = bias+res -> fp32
#define TEN_BYTES 18432              // 128 rows * 72 elems * 2B
#define STAGE_BYTES (4*TEN_BYTES)    // Ah,Al,Bh,Bl
#define GEMM_SMEM (2*STAGE_BYTES)    // 147456
#define ROWB 144                     // smem row stride bytes (72 bf16)

template<int EPI>
__global__ __launch_bounds__(256, 1) void hmma_gemm(
    const __nv_bfloat16* __restrict__ Ah, const __nv_bfloat16* __restrict__ Al,
    const __nv_bfloat16* __restrict__ Bh, const __nv_bfloat16* __restrict__ Bl,
    const float* __restrict__ bias, const float* __restrict__ res,
    float* __restrict__ outF, __nv_bfloat16* __restrict__ outH, __nv_bfloat16* __restrict__ outL,
    int M, int N, int K)
{
    extern __shared__ char smem[];
    const uint32_t sb = smem_u32(smem);

    const int t    = threadIdx.x;
    const int lane = t & 31;
    const int wid  = t >> 5;
    const int warp_m = wid >> 2;          // 0..1
    const int warp_n = wid & 3;           // 0..3
    const int n0 = blockIdx.x * 128;
    const int m0 = blockIdx.y * 128;

    // cp.async source/dest mapping: per tensor, 1024 16B-chunks; 4 per thread.
    const int ldRow = t >> 1;                  // used as: idx = i*256 + t ; row = idx>>3? see below
    (void)ldRow;

    float acc[4][4][4];
    #pragma unroll
    for (int i = 0; i < 4; ++i)
        #pragma unroll
        for (int j = 0; j < 4; ++j)
            #pragma unroll
            for (int e = 0; e < 4; ++e) acc[i][j][e] = 0.f;

    // ldmatrix base addresses (within a stage)
    const uint32_t aBaseH = sb + 0*TEN_BYTES + (uint32_t)(warp_m*64 + (lane & 15)) * ROWB + (lane >> 4) * 16;
    const uint32_t aBaseL = aBaseH + TEN_BYTES;
    const uint32_t bBaseH = sb + 2*TEN_BYTES + (uint32_t)(warp_n*32 + (lane & 7)) * ROWB + ((lane >> 3) & 1) * 16;
    const uint32_t bBaseL = bBaseH + TEN_BYTES;

    const int nch = K >> 6;

    // stage loader
    auto load_stage = [&](int buf, int k0) {
        const uint32_t dst = sb + buf * STAGE_BYTES;
        #pragma unroll
        for (int i = 0; i < 4; ++i) {
            const int idx = i * 256 + t;
            const int row = idx >> 3;          // 0..127
            const int seg = idx & 7;           // 16B segment (8 bf16)
            const uint32_t so = (uint32_t)row * ROWB + seg * 16;
            const size_t ga = (size_t)(m0 + row) * K + k0 + seg * 8;
            const size_t gb = (size_t)(n0 + row) * K + k0 + seg * 8;
            cp16(dst + 0*TEN_BYTES + so, Ah + ga);
            cp16(dst + 1*TEN_BYTES + so, Al + ga);
            cp16(dst + 2*TEN_BYTES + so, Bh + gb);
            cp16(dst + 3*TEN_BYTES + so, Bl + gb);
        }
    };

    load_stage(0, 0);
    CP_COMMIT();

    for (int ch = 0; ch < nch; ++ch) {
        const int cur = ch & 1;
        if (ch + 1 < nch) load_stage(cur ^ 1, (ch + 1) << 6);
        CP_COMMIT();
        CP_WAIT1();
        __syncthreads();

        const uint32_t st = cur * STAGE_BYTES;
        #pragma unroll
        for (int ks = 0; ks < 4; ++ks) {
            const uint32_t kb = ks * 32;       // k16 step -> 32 bytes
            uint32_t ahf[4][4], alf[4][4];
            #pragma unroll
            for (int fm = 0; fm < 4; ++fm) {
                ldm_x4(ahf[fm], aBaseH + st + fm * (16 * ROWB) + kb);
                ldm_x4(alf[fm], aBaseL + st + fm * (16 * ROWB) + kb);
            }
            uint32_t bhf[4][2], blf[4][2];
            #pragma unroll
            for (int fn = 0; fn < 4; ++fn) {
                ldm_x2(bhf[fn], bBaseH + st + fn * (8 * ROWB) + kb);
                ldm_x2(blf[fn], bBaseL + st + fn * (8 * ROWB) + kb);
            }
            #pragma unroll
            for (int fm = 0; fm < 4; ++fm)
                #pragma unroll
                for (int fn = 0; fn < 4; ++fn) {
                    mma_bf16(acc[fm][fn], ahf[fm], bhf[fn]);
                    mma_bf16(acc[fm][fn], ahf[fm], blf[fn]);
                    mma_bf16(acc[fm][fn], alf[fm], bhf[fn]);
                }
        }
        __syncthreads();
    }

    // Epilogue
    #pragma unroll
    for (int fm = 0; fm < 4; ++fm) {
        const int row0 = m0 + warp_m*64 + fm*16 + (lane >> 2);
        #pragma unroll
        for (int fn = 0; fn < 4; ++fn) {
            const int col = n0 + warp_n*32 + fn*8 + (lane & 3)*2;
            const float b0 = bias[col], b1 = bias[col + 1];
            float v0 = acc[fm][fn][0] + b0;
            float v1 = acc[fm][fn][1] + b1;
            float v2 = acc[fm][fn][2] + b0;
            float v3 = acc[fm][fn][3] + b1;
            if (EPI == 2) {
                const float2 r0 = *(const float2*)(res + (size_t)row0 * N + col);
                const float2 r1 = *(const float2*)(res + (size_t)(row0 + 8) * N + col);
                v0 += r0.x; v1 += r0.y; v2 += r1.x; v3 += r1.y;
            }
            if (EPI == 1) {
                v0 = gelu_tanh(v0); v1 = gelu_tanh(v1);
                v2 = gelu_tanh(v2); v3 = gelu_tanh(v3);
                __nv_bfloat16 h0,l0,h1,l1,h2,l2,h3,l3;
                split2(v0,h0,l0); split2(v1,h1,l1); split2(v2,h2,l2); split2(v3,h3,l3);
                *(uint32_t*)(outH + (size_t)row0 * N + col)       = packbf2(h0,h1);
                *(uint32_t*)(outL + (size_t)row0 * N + col)       = packbf2(l0,l1);
                *(uint32_t*)(outH + (size_t)(row0 + 8) * N + col) = packbf2(h2,h3);
                *(uint32_t*)(outL + (size_t)(row0 + 8) * N + col) = packbf2(l2,l3);
            } else {
                *(float2*)(outF + (size_t)row0 * N + col)       = make_float2(v0, v1);
                *(float2*)(outF + (size_t)(row0 + 8) * N + col) = make_float2(v2, v3);
            }
        }
    }
}

// ================= causal flash attention, fp32, 64x64 tiles -> bf16 split out ==========
__global__ __launch_bounds__(256) void attn_kernel(const float* __restrict__ qkv,
                                                   __nv_bfloat16* __restrict__ yh,
                                                   __nv_bfloat16* __restrict__ yl)
{
    __shared__ float Qs [64*64];
    __shared__ float KPs[64*64];
    __shared__ float Vs [64*64];

    const int t  = threadIdx.x;
    const int tx = t & 15;
    const int ty = t >> 4;
    const int qtile = blockIdx.x;
    const int bh = blockIdx.y;
    const int b  = bh / HH;
    const int h  = bh - b * HH;
    const int qbase = qtile * 64;
    const size_t base = (size_t)b * TT * QKVC + (size_t)h * DD;

    {
        const int r  = t >> 2;
        const int d0 = (t & 3) * 16;
        const float* qrow = qkv + base + (size_t)(qbase + r) * QKVC + d0;
        #pragma unroll
        for (int e = 0; e < 16; e += 4) {
            float4 v = *(const float4*)(qrow + e);
            v.x *= 0.125f; v.y *= 0.125f; v.z *= 0.125f; v.w *= 0.125f;
            *(float4*)&Qs[r * 64 + d0 + e] = v;
        }
    }

    float m[4], l[4], o[4][4];
    #pragma unroll
    for (int i = 0; i < 4; ++i) {
        m[i] = -1e30f; l[i] = 0.f;
        #pragma unroll
        for (int j = 0; j < 4; ++j) o[i][j] = 0.f;
    }

    for (int kt = 0; kt <= qtile; ++kt) {
        __syncthreads();
        {
            const int r  = t >> 2;
            const int d0 = (t & 3) * 16;
            const float* krow = qkv + base + CC   + (size_t)(kt*64 + r) * QKVC + d0;
            const float* vrow = qkv + base + 2*CC + (size_t)(kt*64 + r) * QKVC + d0;
            #pragma unroll
            for (int e = 0; e < 16; e += 4) {
                const float4 kv = *(const float4*)(krow + e);
                KPs[(d0+e+0)*64 + r] = kv.x;
                KPs[(d0+e+1)*64 + r] = kv.y;
                KPs[(d0+e+2)*64 + r] = kv.z;
                KPs[(d0+e+3)*64 + r] = kv.w;
                *(float4*)&Vs[r*64 + d0 + e] = *(const float4*)(vrow + e);
            }
        }
        __syncthreads();

        float s[4][4];
        #pragma unroll
        for (int i = 0; i < 4; ++i)
            #pragma unroll
            for (int j = 0; j < 4; ++j) s[i][j] = 0.f;

        #pragma unroll 8
        for (int kk = 0; kk < 64; ++kk) {
            const float4 bb = *(const float4*)&KPs[kk*64 + tx*4];
            #pragma unroll
            for (int i = 0; i < 4; ++i) {
                const float a = Qs[(ty*4+i)*64 + kk];
                s[i][0] = fmaf(a, bb.x, s[i][0]);
                s[i][1] = fmaf(a, bb.y, s[i][1]);
                s[i][2] = fmaf(a, bb.z, s[i][2]);
                s[i][3] = fmaf(a, bb.w, s[i][3]);
            }
        }

        if (kt == qtile) {
            #pragma unroll
            for (int i = 0; i < 4; ++i)
                #pragma unroll
                for (int j = 0; j < 4; ++j)
                    if (tx*4 + j > ty*4 + i) s[i][j] = -1e30f;
        }

        __syncthreads();

        #pragma unroll
        for (int i = 0; i < 4; ++i) {
            float tm = fmaxf(fmaxf(s[i][0], s[i][1]), fmaxf(s[i][2], s[i][3]));
            #pragma unroll
            for (int off = 8; off > 0; off >>= 1)
                tm = fmaxf(tm, __shfl_xor_sync(0xffffffffu, tm, off));
            const float mn = fmaxf(m[i], tm);
            const float alpha = __expf(m[i] - mn);
            float rs = 0.f;
            #pragma unroll
            for (int j = 0; j < 4; ++j) {
                const float p = __expf(s[i][j] - mn);
                s[i][j] = p;
                rs += p;
            }
            #pragma unroll
            for (int off = 8; off > 0; off >>= 1)
                rs += __shfl_xor_sync(0xffffffffu, rs, off);
            l[i] = l[i] * alpha + rs;
            m[i] = mn;
            #pragma unroll
            for (int j = 0; j < 4; ++j) o[i][j] *= alpha;
            *(float4*)&KPs[(ty*4+i)*64 + tx*4] = make_float4(s[i][0], s[i][1], s[i][2], s[i][3]);
        }
        __syncthreads();

        #pragma unroll 8
        for (int kk = 0; kk < 64; ++kk) {
            const float4 vv = *(const float4*)&Vs[kk*64 + tx*4];
            #pragma unroll
            for (int i = 0; i < 4; ++i) {
                const float p = KPs[(ty*4+i)*64 + kk];
                o[i][0] = fmaf(p, vv.x, o[i][0]);
                o[i][1] = fmaf(p, vv.y, o[i][1]);
                o[i][2] = fmaf(p, vv.z, o[i][2]);
                o[i][3] = fmaf(p, vv.w, o[i][3]);
            }
        }
    }

    #pragma unroll
    for (int i = 0; i < 4; ++i) {
        const float inv = 1.0f / l[i];
        const size_t row = (size_t)b * TT + qbase + ty*4 + i;
        const size_t idx = row * CC + h*DD + tx*4;
        __nv_bfloat16 h0,l0,h1,l1,h2,l2,h3,l3;
        split2(o[i][0]*inv, h0, l0);
        split2(o[i][1]*inv, h1, l1);
        split2(o[i][2]*inv, h2, l2);
        split2(o[i][3]*inv, h3, l3);
        *(uint2*)(yh + idx) = make_uint2(packbf2(h0,h1), packbf2(h2,h3));
        *(uint2*)(yl + idx) = make_uint2(packbf2(l0,l1), packbf2(l2,l3));
    }
}

// ================= launch =================
extern "C" void kernel_launch(void* const* d_in, const int* in_sizes, int n_in,
                              void* d_out, int out_size)
{
    const float* x       = (const float*)d_in[0];
    const float* ln1_g   = (const float*)d_in[1];
    const float* ln1_b   = (const float*)d_in[2];
    const float* w_attn  = (const float*)d_in[3];
    const float* b_attn  = (const float*)d_in[4];
    const float* w_aproj = (const float*)d_in[5];
    const float* b_aproj = (const float*)d_in[6];
    const float* ln2_g   = (const float*)d_in[7];
    const float* ln2_b   = (const float*)d_in[8];
    const float* w_fc    = (const float*)d_in[9];
    const float* b_fc    = (const float*)d_in[10];
    const float* w_mproj = (const float*)d_in[11];
    const float* b_mproj = (const float*)d_in[12];
    float* out = (float*)d_out;

    __nv_bfloat16 *h1h,*h1l,*yh,*yl,*h2h,*h2l,*fch,*fcl;
    __nv_bfloat16 *wqh,*wql,*wah,*wal,*wfh,*wfl,*wmh,*wml;
    float *qkv, *x1;
    cudaGetSymbolAddress((void**)&h1h, g_h1h); cudaGetSymbolAddress((void**)&h1l, g_h1l);
    cudaGetSymbolAddress((void**)&qkv, g_qkv);
    cudaGetSymbolAddress((void**)&yh,  g_yh);  cudaGetSymbolAddress((void**)&yl,  g_yl);
    cudaGetSymbolAddress((void**)&x1,  g_x1);
    cudaGetSymbolAddress((void**)&h2h, g_h2h); cudaGetSymbolAddress((void**)&h2l, g_h2l);
    cudaGetSymbolAddress((void**)&fch, g_fch); cudaGetSymbolAddress((void**)&fcl, g_fcl);
    cudaGetSymbolAddress((void**)&wqh, g_wqh); cudaGetSymbolAddress((void**)&wql, g_wql);
    cudaGetSymbolAddress((void**)&wah, g_wah); cudaGetSymbolAddress((void**)&wal, g_wal);
    cudaGetSymbolAddress((void**)&wfh, g_wfh); cudaGetSymbolAddress((void**)&wfl, g_wfl);
    cudaGetSymbolAddress((void**)&wmh, g_wmh); cudaGetSymbolAddress((void**)&wml, g_wml);

    cudaFuncSetAttribute(hmma_gemm<0>, cudaFuncAttributeMaxDynamicSharedMemorySize, GEMM_SMEM);
    cudaFuncSetAttribute(hmma_gemm<1>, cudaFuncAttributeMaxDynamicSharedMemorySize, GEMM_SMEM);
    cudaFuncSetAttribute(hmma_gemm<2>, cudaFuncAttributeMaxDynamicSharedMemorySize, GEMM_SMEM);

    // weight transpose + split
    tsplit_kernel<<<dim3(QKVC/32, CC/32),  dim3(256)>>>(w_attn,  wqh, wql, CC,  QKVC);
    tsplit_kernel<<<dim3(CC/32,   CC/32),  dim3(256)>>>(w_aproj, wah, wal, CC,  CC);
    tsplit_kernel<<<dim3(FFC/32,  CC/32),  dim3(256)>>>(w_fc,    wfh, wfl, CC,  FFC);
    tsplit_kernel<<<dim3(CC/32,   FFC/32), dim3(256)>>>(w_mproj, wmh, wml, FFC, CC);

    // 1) h1 = ln1(x)  (split)
    ln_split_kernel<<<NROWS/8, 256>>>(x, ln1_g, ln1_b, h1h, h1l);
    // 2) qkv = h1 @ w_attn + b_attn
    hmma_gemm<0><<<dim3(QKVC/128, NROWS/128), 256, GEMM_SMEM>>>(
        h1h, h1l, wqh, wql, b_attn, nullptr, qkv, nullptr, nullptr, NROWS, QKVC, CC);
    // 3) y = attention(qkv)  (split)
    attn_kernel<<<dim3(TT/64, BB*HH), 256>>>(qkv, yh, yl);
    // 4) x1 = y @ w_aproj + b_aproj + x
    hmma_gemm<2><<<dim3(CC/128, NROWS/128), 256, GEMM_SMEM>>>(
        yh, yl, wah, wal, b_aproj, x, x1, nullptr, nullptr, NROWS, CC, CC);
    // 5) h2 = ln2(x1)  (split)
    ln_split_kernel<<<NROWS/8, 256>>>(x1, ln2_g, ln2_b, h2h, h2l);
    // 6) fc = gelu(h2 @ w_fc + b_fc)  (split)
    hmma_gemm<1><<<dim3(FFC/128, NROWS/128), 256, GEMM_SMEM>>>(
        h2h, h2l, wfh, wfl, b_fc, nullptr, nullptr, fch, fcl, NROWS, FFC, CC);
    // 7) out = fc @ w_mproj + b_mproj + x1
    hmma_gemm<2><<<dim3(CC/128, NROWS/128), 256, GEMM_SMEM>>>(
        fch, fcl, wmh, wml, b_mproj, x1, out, nullptr, nullptr, NROWS, CC, FFC);
}

// round 4
// speedup vs baseline: 2.6479x; 1.4600x over previous
#include <cuda_runtime.h>
#include <cuda_bf16.h>
#include <math.h>
#include <stdint.h>

// Problem constants
#define BB 4
#define TT 2048
#define CC 768
#define HH 12
#define DD 64
#define NROWS (BB*TT)          // 8192
#define QKVC (3*CC)            // 2304
#define FFC (4*CC)             // 3072

// ================= scratch (allocation-free: __device__ globals) =================
__device__ __nv_bfloat16 g_h1h[NROWS*CC],  g_h1l[NROWS*CC];
__device__ float         g_qkv[NROWS*QKVC];
__device__ __nv_bfloat16 g_yh [NROWS*CC],  g_yl [NROWS*CC];
__device__ float         g_x1 [NROWS*CC];
__device__ __nv_bfloat16 g_h2h[NROWS*CC],  g_h2l[NROWS*CC];
__device__ __nv_bfloat16 g_fch[NROWS*FFC], g_fcl[NROWS*FFC];
__device__ __nv_bfloat16 g_wqh[QKVC*CC], g_wql[QKVC*CC];   // [N][K] K-major
__device__ __nv_bfloat16 g_wah[CC*CC],   g_wal[CC*CC];
__device__ __nv_bfloat16 g_wfh[FFC*CC],  g_wfl[FFC*CC];
__device__ __nv_bfloat16 g_wmh[CC*FFC],  g_wml[CC*FFC];
// per-head split q/k/v: [b*H+h][T][64]
__device__ __nv_bfloat16 g_qsh[NROWS*CC], g_qsl[NROWS*CC];
__device__ __nv_bfloat16 g_ksh[NROWS*CC], g_ksl[NROWS*CC];
__device__ __nv_bfloat16 g_vsh[NROWS*CC], g_vsl[NROWS*CC];

__device__ __forceinline__ void split2(float v, __nv_bfloat16& h, __nv_bfloat16& l) {
    h = __float2bfloat16(v);
    l = __float2bfloat16(v - __bfloat162float(h));
}
__device__ __forceinline__ uint32_t packbf2(__nv_bfloat16 a, __nv_bfloat16 b) {
    return (uint32_t)__bfloat16_as_ushort(a) | ((uint32_t)__bfloat16_as_ushort(b) << 16);
}
__device__ __forceinline__ uint32_t smem_u32(const void* p) {
    uint32_t a;
    asm("{ .reg .u64 t; cvta.to.shared.u64 t, %1; cvt.u32.u64 %0, t; }" : "=r"(a) : "l"(p));
    return a;
}
__device__ __forceinline__ void cp16(uint32_t saddr, const void* g) {
    asm volatile("cp.async.cg.shared.global [%0], [%1], 16;" :: "r"(saddr), "l"(g));
}
#define CP_COMMIT() asm volatile("cp.async.commit_group;" ::: "memory")
#define CP_WAIT1()  asm volatile("cp.async.wait_group 1;" ::: "memory")
#define CP_WAIT0()  asm volatile("cp.async.wait_group 0;" ::: "memory")

__device__ __forceinline__ void ldm_x4(uint32_t* r, uint32_t addr) {
    asm volatile("ldmatrix.sync.aligned.m8n8.x4.shared.b16 {%0,%1,%2,%3}, [%4];"
        : "=r"(r[0]), "=r"(r[1]), "=r"(r[2]), "=r"(r[3]) : "r"(addr));
}
__device__ __forceinline__ void ldm_x4_trans(uint32_t* r, uint32_t addr) {
    asm volatile("ldmatrix.sync.aligned.m8n8.x4.trans.shared.b16 {%0,%1,%2,%3}, [%4];"
        : "=r"(r[0]), "=r"(r[1]), "=r"(r[2]), "=r"(r[3]) : "r"(addr));
}
__device__ __forceinline__ void ldm_x2(uint32_t* r, uint32_t addr) {
    asm volatile("ldmatrix.sync.aligned.m8n8.x2.shared.b16 {%0,%1}, [%2];"
        : "=r"(r[0]), "=r"(r[1]) : "r"(addr));
}
__device__ __forceinline__ void mma_bf16(float* c, const uint32_t* a, const uint32_t* b) {
    asm volatile("mma.sync.aligned.m16n8k16.row.col.f32.bf16.bf16.f32 "
        "{%0,%1,%2,%3}, {%4,%5,%6,%7}, {%8,%9}, {%0,%1,%2,%3};"
        : "+f"(c[0]), "+f"(c[1]), "+f"(c[2]), "+f"(c[3])
        : "r"(a[0]), "r"(a[1]), "r"(a[2]), "r"(a[3]), "r"(b[0]), "r"(b[1]));
}
#define SMEM_SWIZZLE_128B(o) ((o) ^ (((o) >> 3) & 0x70))

__device__ __forceinline__ float gelu_tanh(float v) {
    const float c = 0.7978845608028654f;
    float u = c * (v + 0.044715f * v * v * v);
    return 0.5f * v * (1.0f + tanhf(u));
}

// ================= weight transpose + split: w[K,N] -> wt_hi/lo[N,K] =================
__global__ __launch_bounds__(256) void tsplit_kernel(const float* __restrict__ w,
                                                     __nv_bfloat16* __restrict__ th,
                                                     __nv_bfloat16* __restrict__ tl,
                                                     int K, int N)
{
    __shared__ float tile[32][33];
    const int tx = threadIdx.x & 31, ty = threadIdx.x >> 5;   // 32x8
    const int n0 = blockIdx.x * 32, k0 = blockIdx.y * 32;
    #pragma unroll
    for (int r = 0; r < 4; ++r)
        tile[ty + 8*r][tx] = w[(size_t)(k0 + ty + 8*r) * N + n0 + tx];
    __syncthreads();
    #pragma unroll
    for (int r = 0; r < 4; ++r) {
        const float v = tile[tx][ty + 8*r];
        __nv_bfloat16 h, l; split2(v, h, l);
        const size_t o = (size_t)(n0 + ty + 8*r) * K + k0 + tx;
        th[o] = h; tl[o] = l;
    }
}

// ================= LayerNorm -> bf16 split =================
__global__ __launch_bounds__(256) void ln_split_kernel(const float* __restrict__ x,
                                                       const float* __restrict__ g,
                                                       const float* __restrict__ bt,
                                                       __nv_bfloat16* __restrict__ oh,
                                                       __nv_bfloat16* __restrict__ ol)
{
    const int row  = blockIdx.x * 8 + (threadIdx.x >> 5);
    const int lane = threadIdx.x & 31;
    const float* xr = x + (size_t)row * CC;

    float4 v[6];
    float sum = 0.f;
    #pragma unroll
    for (int i = 0; i < 6; ++i) {
        v[i] = *(const float4*)(xr + lane*4 + i*128);
        sum += (v[i].x + v[i].y) + (v[i].z + v[i].w);
    }
    #pragma unroll
    for (int off = 16; off > 0; off >>= 1) sum += __shfl_xor_sync(0xffffffffu, sum, off);
    const float mu = sum * (1.0f/768.0f);
    float var = 0.f;
    #pragma unroll
    for (int i = 0; i < 6; ++i) {
        float dx;
        dx = v[i].x - mu; var += dx*dx;  dx = v[i].y - mu; var += dx*dx;
        dx = v[i].z - mu; var += dx*dx;  dx = v[i].w - mu; var += dx*dx;
    }
    #pragma unroll
    for (int off = 16; off > 0; off >>= 1) var += __shfl_xor_sync(0xffffffffu, var, off);
    const float rstd = rsqrtf(var * (1.0f/768.0f) + 1e-5f);

    #pragma unroll
    for (int i = 0; i < 6; ++i) {
        const int col = lane*4 + i*128;
        const float4 gg = *(const float4*)(g  + col);
        const float4 bb = *(const float4*)(bt + col);
        float r0 = (v[i].x - mu)*rstd*gg.x + bb.x;
        float r1 = (v[i].y - mu)*rstd*gg.y + bb.y;
        float r2 = (v[i].z - mu)*rstd*gg.z + bb.z;
        float r3 = (v[i].w - mu)*rstd*gg.w + bb.w;
        __nv_bfloat16 h0,l0,h1,l1,h2,l2,h3,l3;
        split2(r0,h0,l0); split2(r1,h1,l1); split2(r2,h2,l2); split2(r3,h3,l3);
        const size_t o = (size_t)row * CC + col;
        *(uint2*)(oh + o) = make_uint2(packbf2(h0,h1), packbf2(h2,h3));
        *(uint2*)(ol + o) = make_uint2(packbf2(l0,l1), packbf2(l2,l3));
    }
}

// ================= qkv fp32 -> per-head split bf16 (Q pre-scaled) =================
__global__ __launch_bounds__(256) void cvt_qkv(const float* __restrict__ qkv,
    __nv_bfloat16* __restrict__ qh, __nv_bfloat16* __restrict__ ql,
    __nv_bfloat16* __restrict__ kh, __nv_bfloat16* __restrict__ kl,
    __nv_bfloat16* __restrict__ vh, __nv_bfloat16* __restrict__ vl)
{
    const size_t i4 = ((size_t)blockIdx.x * 256 + threadIdx.x) * 4;
    const int row = (int)(i4 / QKVC);
    const int c   = (int)(i4 % QKVC);
    const int which = c / CC;
    const int cc = c - which * CC;
    const int h = cc >> 6, d = cc & 63;
    const int b = row / TT, tp = row - b * TT;
    float4 v = *(const float4*)(qkv + i4);
    if (which == 0) { v.x *= 0.125f; v.y *= 0.125f; v.z *= 0.125f; v.w *= 0.125f; }
    __nv_bfloat16 h0,l0,h1,l1,h2,l2,h3,l3;
    split2(v.x,h0,l0); split2(v.y,h1,l1); split2(v.z,h2,l2); split2(v.w,h3,l3);
    const size_t o = ((size_t)(b * HH + h) * TT + tp) * 64 + d;
    __nv_bfloat16* oh = (which == 0) ? qh : (which == 1) ? kh : vh;
    __nv_bfloat16* ol = (which == 0) ? ql : (which == 1) ? kl : vl;
    *(uint2*)(oh + o) = make_uint2(packbf2(h0,h1), packbf2(h2,h3));
    *(uint2*)(ol + o) = make_uint2(packbf2(l0,l1), packbf2(l2,l3));
}

// ================= split-bf16 HMMA GEMM (unchanged from R3) =================
#define TEN_BYTES 18432              // 128 rows * 72 elems * 2B
#define STAGE_BYTES (4*TEN_BYTES)
#define GEMM_SMEM (2*STAGE_BYTES)    // 147456
#define ROWB 144

template<int EPI>
__global__ __launch_bounds__(256, 1) void hmma_gemm(
    const __nv_bfloat16* __restrict__ Ah, const __nv_bfloat16* __restrict__ Al,
    const __nv_bfloat16* __restrict__ Bh, const __nv_bfloat16* __restrict__ Bl,
    const float* __restrict__ bias, const float* __restrict__ res,
    float* __restrict__ outF, __nv_bfloat16* __restrict__ outH, __nv_bfloat16* __restrict__ outL,
    int M, int N, int K)
{
    extern __shared__ char smem[];
    const uint32_t sb = smem_u32(smem);

    const int t    = threadIdx.x;
    const int lane = t & 31;
    const int wid  = t >> 5;
    const int warp_m = wid >> 2;
    const int warp_n = wid & 3;
    const int n0 = blockIdx.x * 128;
    const int m0 = blockIdx.y * 128;

    float acc[4][4][4];
    #pragma unroll
    for (int i = 0; i < 4; ++i)
        #pragma unroll
        for (int j = 0; j < 4; ++j)
            #pragma unroll
            for (int e = 0; e < 4; ++e) acc[i][j][e] = 0.f;

    const uint32_t aBaseH = sb + 0*TEN_BYTES + (uint32_t)(warp_m*64 + (lane & 15)) * ROWB + (lane >> 4) * 16;
    const uint32_t aBaseL = aBaseH + TEN_BYTES;
    const uint32_t bBaseH = sb + 2*TEN_BYTES + (uint32_t)(warp_n*32 + (lane & 7)) * ROWB + ((lane >> 3) & 1) * 16;
    const uint32_t bBaseL = bBaseH + TEN_BYTES;

    const int nch = K >> 6;

    auto load_stage = [&](int buf, int k0) {
        const uint32_t dst = sb + buf * STAGE_BYTES;
        #pragma unroll
        for (int i = 0; i < 4; ++i) {
            const int idx = i * 256 + t;
            const int row = idx >> 3;
            const int seg = idx & 7;
            const uint32_t so = (uint32_t)row * ROWB + seg * 16;
            const size_t ga = (size_t)(m0 + row) * K + k0 + seg * 8;
            const size_t gb = (size_t)(n0 + row) * K + k0 + seg * 8;
            cp16(dst + 0*TEN_BYTES + so, Ah + ga);
            cp16(dst + 1*TEN_BYTES + so, Al + ga);
            cp16(dst + 2*TEN_BYTES + so, Bh + gb);
            cp16(dst + 3*TEN_BYTES + so, Bl + gb);
        }
    };

    load_stage(0, 0);
    CP_COMMIT();

    for (int ch = 0; ch < nch; ++ch) {
        const int cur = ch & 1;
        if (ch + 1 < nch) load_stage(cur ^ 1, (ch + 1) << 6);
        CP_COMMIT();
        CP_WAIT1();
        __syncthreads();

        const uint32_t st = cur * STAGE_BYTES;
        #pragma unroll
        for (int ks = 0; ks < 4; ++ks) {
            const uint32_t kb = ks * 32;
            uint32_t ahf[4][4], alf[4][4];
            #pragma unroll
            for (int fm = 0; fm < 4; ++fm) {
                ldm_x4(ahf[fm], aBaseH + st + fm * (16 * ROWB) + kb);
                ldm_x4(alf[fm], aBaseL + st + fm * (16 * ROWB) + kb);
            }
            uint32_t bhf[4][2], blf[4][2];
            #pragma unroll
            for (int fn = 0; fn < 4; ++fn) {
                ldm_x2(bhf[fn], bBaseH + st + fn * (8 * ROWB) + kb);
                ldm_x2(blf[fn], bBaseL + st + fn * (8 * ROWB) + kb);
            }
            #pragma unroll
            for (int fm = 0; fm < 4; ++fm)
                #pragma unroll
                for (int fn = 0; fn < 4; ++fn) {
                    mma_bf16(acc[fm][fn], ahf[fm], bhf[fn]);
                    mma_bf16(acc[fm][fn], ahf[fm], blf[fn]);
                    mma_bf16(acc[fm][fn], alf[fm], bhf[fn]);
                }
        }
        __syncthreads();
    }

    #pragma unroll
    for (int fm = 0; fm < 4; ++fm) {
        const int row0 = m0 + warp_m*64 + fm*16 + (lane >> 2);
        #pragma unroll
        for (int fn = 0; fn < 4; ++fn) {
            const int col = n0 + warp_n*32 + fn*8 + (lane & 3)*2;
            const float b0 = bias[col], b1 = bias[col + 1];
            float v0 = acc[fm][fn][0] + b0;
            float v1 = acc[fm][fn][1] + b1;
            float v2 = acc[fm][fn][2] + b0;
            float v3 = acc[fm][fn][3] + b1;
            if (EPI == 2) {
                const float2 r0 = *(const float2*)(res + (size_t)row0 * N + col);
                const float2 r1 = *(const float2*)(res + (size_t)(row0 + 8) * N + col);
                v0 += r0.x; v1 += r0.y; v2 += r1.x; v3 += r1.y;
            }
            if (EPI == 1) {
                v0 = gelu_tanh(v0); v1 = gelu_tanh(v1);
                v2 = gelu_tanh(v2); v3 = gelu_tanh(v3);
                __nv_bfloat16 h0,l0,h1,l1,h2,l2,h3,l3;
                split2(v0,h0,l0); split2(v1,h1,l1); split2(v2,h2,l2); split2(v3,h3,l3);
                *(uint32_t*)(outH + (size_t)row0 * N + col)       = packbf2(h0,h1);
                *(uint32_t*)(outL + (size_t)row0 * N + col)       = packbf2(l0,l1);
                *(uint32_t*)(outH + (size_t)(row0 + 8) * N + col) = packbf2(h2,h3);
                *(uint32_t*)(outL + (size_t)(row0 + 8) * N + col) = packbf2(l2,l3);
            } else {
                *(float2*)(outF + (size_t)row0 * N + col)       = make_float2(v0, v1);
                *(float2*)(outF + (size_t)(row0 + 8) * N + col) = make_float2(v2, v3);
            }
        }
    }
}

// ================= split-bf16 HMMA flash attention =================
// Q-tile 128 rows (8 warps x m16), K-tile 64, per-head layout [bh][T][64].
// smem: Qh 16K | Ql 16K | 2 KV stages of (Kh 8K | Kl 8K | Vh 8K | Vl 8K)
#define ATT_SMEM 98304
__global__ __launch_bounds__(256, 1) void attn_mma(
    const __nv_bfloat16* __restrict__ qh, const __nv_bfloat16* __restrict__ ql,
    const __nv_bfloat16* __restrict__ kh, const __nv_bfloat16* __restrict__ kl,
    const __nv_bfloat16* __restrict__ vh, const __nv_bfloat16* __restrict__ vl,
    __nv_bfloat16* __restrict__ yh, __nv_bfloat16* __restrict__ yl)
{
    extern __shared__ char smem[];
    const uint32_t sb = smem_u32(smem);
    enum { QH_O = 0, QL_O = 16384, KV0 = 32768, KV_STRIDE = 32768,
           KH_O = 0, KL_O = 8192, VH_O = 16384, VL_O = 24576 };

    const int t = threadIdx.x, lane = t & 31, wid = t >> 5;
    const int qt = (int)(gridDim.x - 1) - (int)blockIdx.x;   // big tiles first
    const int bh = blockIdx.y;
    const int qbase = qt * 128;
    const size_t hb = (size_t)bh * TT * 64;
    const int warpQ = wid * 16;

    // Q copy (1024 chunks per tensor)
    #pragma unroll
    for (int i = 0; i < 4; ++i) {
        const int idx = t + i * 256;
        const int row = idx >> 3, seg = idx & 7;
        const uint32_t so = SMEM_SWIZZLE_128B((uint32_t)(row * 128 + seg * 16));
        const size_t g = hb + (size_t)(qbase + row) * 64 + seg * 8;
        cp16(sb + QH_O + so, qh + g);
        cp16(sb + QL_O + so, ql + g);
    }
    auto load_kv = [&](int buf, int kt) {
        const uint32_t dst = sb + KV0 + buf * KV_STRIDE;
        #pragma unroll
        for (int i = 0; i < 2; ++i) {
            const int idx = t + i * 256;
            const int row = idx >> 3, seg = idx & 7;
            const uint32_t so = SMEM_SWIZZLE_128B((uint32_t)(row * 128 + seg * 16));
            const size_t g = hb + (size_t)(kt * 64 + row) * 64 + seg * 8;
            cp16(dst + KH_O + so, kh + g);
            cp16(dst + KL_O + so, kl + g);
            cp16(dst + VH_O + so, vh + g);
            cp16(dst + VL_O + so, vl + g);
        }
    };
    load_kv(0, 0);
    CP_COMMIT();

    uint32_t qah[4][4], qal[4][4];
    float o[8][4];
    #pragma unroll
    for (int j = 0; j < 8; ++j)
        #pragma unroll
        for (int e = 0; e < 4; ++e) o[j][e] = 0.f;
    float m0r = -1e30f, m1r = -1e30f, l0r = 0.f, l1r = 0.f;

    const int nkt = 2 * qt + 2;
    for (int kt = 0; kt < nkt; ++kt) {
        const int buf = kt & 1;
        if (kt + 1 < nkt) { load_kv(buf ^ 1, kt + 1); CP_COMMIT(); CP_WAIT1(); }
        else { CP_WAIT0(); }
        __syncthreads();

        if (kt == 0) {
            const uint32_t qrow = (uint32_t)(warpQ + (lane & 15));
            const uint32_t qbyt = (uint32_t)((lane >> 4) * 16);
            #pragma unroll
            for (int s = 0; s < 4; ++s) {
                const uint32_t so = SMEM_SWIZZLE_128B(qrow * 128 + s * 32 + qbyt);
                ldm_x4(qah[s], sb + QH_O + so);
                ldm_x4(qal[s], sb + QL_O + so);
            }
        }
        const uint32_t st = sb + KV0 + buf * KV_STRIDE;

        // ---- S = Q K^T (3-term split) ----
        float sacc[8][4];
        #pragma unroll
        for (int j = 0; j < 8; ++j) { sacc[j][0]=0.f; sacc[j][1]=0.f; sacc[j][2]=0.f; sacc[j][3]=0.f; }
        #pragma unroll
        for (int j = 0; j < 8; ++j) {
            const uint32_t krow = (uint32_t)(j * 8 + (lane & 7));
            const uint32_t kbyt = (uint32_t)(((lane >> 3) & 3) * 16);
            const uint32_t so0 = SMEM_SWIZZLE_128B(krow * 128 + kbyt);
            const uint32_t so1 = SMEM_SWIZZLE_128B(krow * 128 + 64 + kbyt);
            uint32_t kbh0[4], kbh1[4], kbl0[4], kbl1[4];
            ldm_x4(kbh0, st + KH_O + so0);
            ldm_x4(kbh1, st + KH_O + so1);
            ldm_x4(kbl0, st + KL_O + so0);
            ldm_x4(kbl1, st + KL_O + so1);
            mma_bf16(sacc[j], qah[0], kbh0 + 0); mma_bf16(sacc[j], qah[1], kbh0 + 2);
            mma_bf16(sacc[j], qah[2], kbh1 + 0); mma_bf16(sacc[j], qah[3], kbh1 + 2);
            mma_bf16(sacc[j], qah[0], kbl0 + 0); mma_bf16(sacc[j], qah[1], kbl0 + 2);
            mma_bf16(sacc[j], qah[2], kbl1 + 0); mma_bf16(sacc[j], qah[3], kbl1 + 2);
            mma_bf16(sacc[j], qal[0], kbh0 + 0); mma_bf16(sacc[j], qal[1], kbh0 + 2);
            mma_bf16(sacc[j], qal[2], kbh1 + 0); mma_bf16(sacc[j], qal[3], kbh1 + 2);
        }

        // ---- causal mask (last two K-tiles only) ----
        if (kt >= 2 * qt) {
            const int r0 = qbase + warpQ + (lane >> 2);
            #pragma unroll
            for (int j = 0; j < 8; ++j) {
                const int c = kt * 64 + j * 8 + (lane & 3) * 2;
                if (c     > r0)     sacc[j][0] = -1e30f;
                if (c + 1 > r0)     sacc[j][1] = -1e30f;
                if (c     > r0 + 8) sacc[j][2] = -1e30f;
                if (c + 1 > r0 + 8) sacc[j][3] = -1e30f;
            }
        }

        // ---- online softmax ----
        float tm0 = -1e30f, tm1 = -1e30f;
        #pragma unroll
        for (int j = 0; j < 8; ++j) {
            tm0 = fmaxf(tm0, fmaxf(sacc[j][0], sacc[j][1]));
            tm1 = fmaxf(tm1, fmaxf(sacc[j][2], sacc[j][3]));
        }
        tm0 = fmaxf(tm0, __shfl_xor_sync(0xffffffffu, tm0, 1));
        tm0 = fmaxf(tm0, __shfl_xor_sync(0xffffffffu, tm0, 2));
        tm1 = fmaxf(tm1, __shfl_xor_sync(0xffffffffu, tm1, 1));
        tm1 = fmaxf(tm1, __shfl_xor_sync(0xffffffffu, tm1, 2));
        const float mn0 = fmaxf(m0r, tm0), mn1 = fmaxf(m1r, tm1);
        const float al0 = __expf(m0r - mn0), al1 = __expf(m1r - mn1);
        m0r = mn0; m1r = mn1;
        float rs0 = 0.f, rs1 = 0.f;
        #pragma unroll
        for (int j = 0; j < 8; ++j) {
            sacc[j][0] = __expf(sacc[j][0] - mn0);
            sacc[j][1] = __expf(sacc[j][1] - mn0);
            sacc[j][2] = __expf(sacc[j][2] - mn1);
            sacc[j][3] = __expf(sacc[j][3] - mn1);
            rs0 += sacc[j][0] + sacc[j][1];
            rs1 += sacc[j][2] + sacc[j][3];
        }
        rs0 += __shfl_xor_sync(0xffffffffu, rs0, 1);
        rs0 += __shfl_xor_sync(0xffffffffu, rs0, 2);
        rs1 += __shfl_xor_sync(0xffffffffu, rs1, 1);
        rs1 += __shfl_xor_sync(0xffffffffu, rs1, 2);
        l0r = l0r * al0 + rs0;
        l1r = l1r * al1 + rs1;
        #pragma unroll
        for (int j = 0; j < 8; ++j) {
            o[j][0] *= al0; o[j][1] *= al0; o[j][2] *= al1; o[j][3] *= al1;
        }

        // ---- P -> split A-operand fragments (direct re-pack) ----
        uint32_t pah[4][4], pal[4][4];
        #pragma unroll
        for (int s = 0; s < 4; ++s) {
            __nv_bfloat16 h0, l0, h1, l1;
            split2(sacc[2*s][0], h0, l0);   split2(sacc[2*s][1], h1, l1);
            pah[s][0] = packbf2(h0, h1);    pal[s][0] = packbf2(l0, l1);
            split2(sacc[2*s][2], h0, l0);   split2(sacc[2*s][3], h1, l1);
            pah[s][1] = packbf2(h0, h1);    pal[s][1] = packbf2(l0, l1);
            split2(sacc[2*s+1][0], h0, l0); split2(sacc[2*s+1][1], h1, l1);
            pah[s][2] = packbf2(h0, h1);    pal[s][2] = packbf2(l0, l1);
            split2(sacc[2*s+1][2], h0, l0); split2(sacc[2*s+1][3], h1, l1);
            pah[s][3] = packbf2(h0, h1);    pal[s][3] = packbf2(l0, l1);
        }

        // ---- O += P V (3-term split, V^T via ldmatrix.trans) ----
        #pragma unroll
        for (int jp = 0; jp < 4; ++jp) {
            #pragma unroll
            for (int s = 0; s < 4; ++s) {
                const uint32_t vrow = (uint32_t)(s * 16 + (lane & 15));
                const uint32_t vbyt = (uint32_t)(jp * 32 + (lane >> 4) * 16);
                const uint32_t so = SMEM_SWIZZLE_128B(vrow * 128 + vbyt);
                uint32_t vbh[4], vbl[4];
                ldm_x4_trans(vbh, st + VH_O + so);
                ldm_x4_trans(vbl, st + VL_O + so);
                mma_bf16(o[2*jp],     pah[s], vbh + 0);
                mma_bf16(o[2*jp + 1], pah[s], vbh + 2);
                mma_bf16(o[2*jp],     pah[s], vbl + 0);
                mma_bf16(o[2*jp + 1], pah[s], vbl + 2);
                mma_bf16(o[2*jp],     pal[s], vbh + 0);
                mma_bf16(o[2*jp + 1], pal[s], vbh + 2);
            }
        }
        __syncthreads();
    }

    // ---- epilogue: normalize, split, write y ----
    const float inv0 = 1.0f / l0r, inv1 = 1.0f / l1r;
    const int b = bh / HH, h = bh - b * HH;
    const size_t row0 = (size_t)b * TT + qbase + warpQ + (lane >> 2);
    #pragma unroll
    for (int j = 0; j < 8; ++j) {
        const int col = h * 64 + j * 8 + (lane & 3) * 2;
        __nv_bfloat16 h0, l0, h1, l1;
        split2(o[j][0] * inv0, h0, l0); split2(o[j][1] * inv0, h1, l1);
        *(uint32_t*)(yh + row0 * CC + col) = packbf2(h0, h1);
        *(uint32_t*)(yl + row0 * CC + col) = packbf2(l0, l1);
        split2(o[j][2] * inv1, h0, l0); split2(o[j][3] * inv1, h1, l1);
        *(uint32_t*)(yh + (row0 + 8) * CC + col) = packbf2(h0, h1);
        *(uint32_t*)(yl + (row0 + 8) * CC + col) = packbf2(l0, l1);
    }
}

// ================= launch =================
extern "C" void kernel_launch(void* const* d_in, const int* in_sizes, int n_in,
                              void* d_out, int out_size)
{
    const float* x       = (const float*)d_in[0];
    const float* ln1_g   = (const float*)d_in[1];
    const float* ln1_b   = (const float*)d_in[2];
    const float* w_attn  = (const float*)d_in[3];
    const float* b_attn  = (const float*)d_in[4];
    const float* w_aproj = (const float*)d_in[5];
    const float* b_aproj = (const float*)d_in[6];
    const float* ln2_g   = (const float*)d_in[7];
    const float* ln2_b   = (const float*)d_in[8];
    const float* w_fc    = (const float*)d_in[9];
    const float* b_fc    = (const float*)d_in[10];
    const float* w_mproj = (const float*)d_in[11];
    const float* b_mproj = (const float*)d_in[12];
    float* out = (float*)d_out;

    __nv_bfloat16 *h1h,*h1l,*yh,*yl,*h2h,*h2l,*fch,*fcl;
    __nv_bfloat16 *wqh,*wql,*wah,*wal,*wfh,*wfl,*wmh,*wml;
    __nv_bfloat16 *qsh,*qsl,*ksh,*ksl,*vsh,*vsl;
    float *qkv, *x1;
    cudaGetSymbolAddress((void**)&h1h, g_h1h); cudaGetSymbolAddress((void**)&h1l, g_h1l);
    cudaGetSymbolAddress((void**)&qkv, g_qkv);
    cudaGetSymbolAddress((void**)&yh,  g_yh);  cudaGetSymbolAddress((void**)&yl,  g_yl);
    cudaGetSymbolAddress((void**)&x1,  g_x1);
    cudaGetSymbolAddress((void**)&h2h, g_h2h); cudaGetSymbolAddress((void**)&h2l, g_h2l);
    cudaGetSymbolAddress((void**)&fch, g_fch); cudaGetSymbolAddress((void**)&fcl, g_fcl);
    cudaGetSymbolAddress((void**)&wqh, g_wqh); cudaGetSymbolAddress((void**)&wql, g_wql);
    cudaGetSymbolAddress((void**)&wah, g_wah); cudaGetSymbolAddress((void**)&wal, g_wal);
    cudaGetSymbolAddress((void**)&wfh, g_wfh); cudaGetSymbolAddress((void**)&wfl, g_wfl);
    cudaGetSymbolAddress((void**)&wmh, g_wmh); cudaGetSymbolAddress((void**)&wml, g_wml);
    cudaGetSymbolAddress((void**)&qsh, g_qsh); cudaGetSymbolAddress((void**)&qsl, g_qsl);
    cudaGetSymbolAddress((void**)&ksh, g_ksh); cudaGetSymbolAddress((void**)&ksl, g_ksl);
    cudaGetSymbolAddress((void**)&vsh, g_vsh); cudaGetSymbolAddress((void**)&vsl, g_vsl);

    cudaFuncSetAttribute(hmma_gemm<0>, cudaFuncAttributeMaxDynamicSharedMemorySize, GEMM_SMEM);
    cudaFuncSetAttribute(hmma_gemm<1>, cudaFuncAttributeMaxDynamicSharedMemorySize, GEMM_SMEM);
    cudaFuncSetAttribute(hmma_gemm<2>, cudaFuncAttributeMaxDynamicSharedMemorySize, GEMM_SMEM);
    cudaFuncSetAttribute(attn_mma,     cudaFuncAttributeMaxDynamicSharedMemorySize, ATT_SMEM);

    // weight transpose + split
    tsplit_kernel<<<dim3(QKVC/32, CC/32),  dim3(256)>>>(w_attn,  wqh, wql, CC,  QKVC);
    tsplit_kernel<<<dim3(CC/32,   CC/32),  dim3(256)>>>(w_aproj, wah, wal, CC,  CC);
    tsplit_kernel<<<dim3(FFC/32,  CC/32),  dim3(256)>>>(w_fc,    wfh, wfl, CC,  FFC);
    tsplit_kernel<<<dim3(CC/32,   FFC/32), dim3(256)>>>(w_mproj, wmh, wml, FFC, CC);

    // 1) h1 = ln1(x)  (split)
    ln_split_kernel<<<NROWS/8, 256>>>(x, ln1_g, ln1_b, h1h, h1l);
    // 2) qkv = h1 @ w_attn + b_attn
    hmma_gemm<0><<<dim3(QKVC/128, NROWS/128), 256, GEMM_SMEM>>>(
        h1h, h1l, wqh, wql, b_attn, nullptr, qkv, nullptr, nullptr, NROWS, QKVC, CC);
    // 3) qkv -> per-head split bf16
    cvt_qkv<<<(NROWS*QKVC)/(256*4), 256>>>(qkv, qsh, qsl, ksh, ksl, vsh, vsl);
    // 4) y = attention (HMMA flash)
    attn_mma<<<dim3(TT/128, BB*HH), 256, ATT_SMEM>>>(qsh, qsl, ksh, ksl, vsh, vsl, yh, yl);
    // 5) x1 = y @ w_aproj + b_aproj + x
    hmma_gemm<2><<<dim3(CC/128, NROWS/128), 256, GEMM_SMEM>>>(
        yh, yl, wah, wal, b_aproj, x, x1, nullptr, nullptr, NROWS, CC, CC);
    // 6) h2 = ln2(x1)  (split)
    ln_split_kernel<<<NROWS/8, 256>>>(x1, ln2_g, ln2_b, h2h, h2l);
    // 7) fc = gelu(h2 @ w_fc + b_fc)  (split)
    hmma_gemm<1><<<dim3(FFC/128, NROWS/128), 256, GEMM_SMEM>>>(
        h2h, h2l, wfh, wfl, b_fc, nullptr, nullptr, fch, fcl, NROWS, FFC, CC);
    // 8) out = fc @ w_mproj + b_mproj + x1
    hmma_gemm<2><<<dim3(CC/128, NROWS/128), 256, GEMM_SMEM>>>(
        fch, fcl, wmh, wml, b_mproj, x1, out, nullptr, nullptr, NROWS, CC, FFC);
}

// round 5
// speedup vs baseline: 2.6713x; 1.0089x over previous
#include <cuda_runtime.h>
#include <cuda_bf16.h>
#include <math.h>
#include <stdint.h>

// Problem constants
#define BB 4
#define TT 2048
#define CC 768
#define HH 12
#define DD 64
#define NROWS (BB*TT)          // 8192
#define QKVC (3*CC)            // 2304
#define FFC (4*CC)             // 3072

#define QSCALE (0.125f * 1.4426950408889634f)   // 1/sqrt(D) * log2(e)

// ================= scratch (allocation-free: __device__ globals) =================
__device__ __nv_bfloat16 g_h1h[NROWS*CC],  g_h1l[NROWS*CC];
__device__ __nv_bfloat16 g_yh [NROWS*CC],  g_yl [NROWS*CC];
__device__ float         g_x1 [NROWS*CC];
__device__ __nv_bfloat16 g_h2h[NROWS*CC],  g_h2l[NROWS*CC];
__device__ __nv_bfloat16 g_fch[NROWS*FFC], g_fcl[NROWS*FFC];
__device__ __nv_bfloat16 g_wqh[QKVC*CC], g_wql[QKVC*CC];   // [N][K] K-major
__device__ __nv_bfloat16 g_wah[CC*CC],   g_wal[CC*CC];
__device__ __nv_bfloat16 g_wfh[FFC*CC],  g_wfl[FFC*CC];
__device__ __nv_bfloat16 g_wmh[CC*FFC],  g_wml[CC*FFC];
// per-head split q/k/v: [b*H+h][T][64]
__device__ __nv_bfloat16 g_qsh[NROWS*CC], g_qsl[NROWS*CC];
__device__ __nv_bfloat16 g_ksh[NROWS*CC], g_ksl[NROWS*CC];
__device__ __nv_bfloat16 g_vsh[NROWS*CC], g_vsl[NROWS*CC];

__device__ __forceinline__ void split2(float v, __nv_bfloat16& h, __nv_bfloat16& l) {
    h = __float2bfloat16(v);
    l = __float2bfloat16(v - __bfloat162float(h));
}
__device__ __forceinline__ uint32_t packbf2(__nv_bfloat16 a, __nv_bfloat16 b) {
    return (uint32_t)__bfloat16_as_ushort(a) | ((uint32_t)__bfloat16_as_ushort(b) << 16);
}
__device__ __forceinline__ uint32_t smem_u32(const void* p) {
    uint32_t a;
    asm("{ .reg .u64 t; cvta.to.shared.u64 t, %1; cvt.u32.u64 %0, t; }" : "=r"(a) : "l"(p));
    return a;
}
__device__ __forceinline__ void cp16(uint32_t saddr, const void* g) {
    asm volatile("cp.async.cg.shared.global [%0], [%1], 16;" :: "r"(saddr), "l"(g));
}
#define CP_COMMIT() asm volatile("cp.async.commit_group;" ::: "memory")
#define CP_WAIT1()  asm volatile("cp.async.wait_group 1;" ::: "memory")
#define CP_WAIT0()  asm volatile("cp.async.wait_group 0;" ::: "memory")

__device__ __forceinline__ void ldm_x4(uint32_t* r, uint32_t addr) {
    asm volatile("ldmatrix.sync.aligned.m8n8.x4.shared.b16 {%0,%1,%2,%3}, [%4];"
        : "=r"(r[0]), "=r"(r[1]), "=r"(r[2]), "=r"(r[3]) : "r"(addr));
}
__device__ __forceinline__ void ldm_x4_trans(uint32_t* r, uint32_t addr) {
    asm volatile("ldmatrix.sync.aligned.m8n8.x4.trans.shared.b16 {%0,%1,%2,%3}, [%4];"
        : "=r"(r[0]), "=r"(r[1]), "=r"(r[2]), "=r"(r[3]) : "r"(addr));
}
__device__ __forceinline__ void ldm_x2(uint32_t* r, uint32_t addr) {
    asm volatile("ldmatrix.sync.aligned.m8n8.x2.shared.b16 {%0,%1}, [%2];"
        : "=r"(r[0]), "=r"(r[1]) : "r"(addr));
}
__device__ __forceinline__ void mma_bf16(float* c, const uint32_t* a, const uint32_t* b) {
    asm volatile("mma.sync.aligned.m16n8k16.row.col.f32.bf16.bf16.f32 "
        "{%0,%1,%2,%3}, {%4,%5,%6,%7}, {%8,%9}, {%0,%1,%2,%3};"
        : "+f"(c[0]), "+f"(c[1]), "+f"(c[2]), "+f"(c[3])
        : "r"(a[0]), "r"(a[1]), "r"(a[2]), "r"(a[3]), "r"(b[0]), "r"(b[1]));
}
#define SMEM_SWIZZLE_128B(o) ((o) ^ (((o) >> 3) & 0x70))

__device__ __forceinline__ float gelu_tanh(float v) {
    const float c = 0.7978845608028654f;
    float u = c * (v + 0.044715f * v * v * v);
    return 0.5f * v * (1.0f + tanhf(u));
}

// ================= weight transpose + split: w[K,N] -> wt_hi/lo[N,K] =================
__global__ __launch_bounds__(256) void tsplit_kernel(const float* __restrict__ w,
                                                     __nv_bfloat16* __restrict__ th,
                                                     __nv_bfloat16* __restrict__ tl,
                                                     int K, int N)
{
    __shared__ float tile[32][33];
    const int tx = threadIdx.x & 31, ty = threadIdx.x >> 5;   // 32x8
    const int n0 = blockIdx.x * 32, k0 = blockIdx.y * 32;
    #pragma unroll
    for (int r = 0; r < 4; ++r)
        tile[ty + 8*r][tx] = w[(size_t)(k0 + ty + 8*r) * N + n0 + tx];
    __syncthreads();
    #pragma unroll
    for (int r = 0; r < 4; ++r) {
        const float v = tile[tx][ty + 8*r];
        __nv_bfloat16 h, l; split2(v, h, l);
        const size_t o = (size_t)(n0 + ty + 8*r) * K + k0 + tx;
        th[o] = h; tl[o] = l;
    }
}

// ================= LayerNorm -> bf16 split =================
__global__ __launch_bounds__(256) void ln_split_kernel(const float* __restrict__ x,
                                                       const float* __restrict__ g,
                                                       const float* __restrict__ bt,
                                                       __nv_bfloat16* __restrict__ oh,
                                                       __nv_bfloat16* __restrict__ ol)
{
    const int row  = blockIdx.x * 8 + (threadIdx.x >> 5);
    const int lane = threadIdx.x & 31;
    const float* xr = x + (size_t)row * CC;

    float4 v[6];
    float sum = 0.f;
    #pragma unroll
    for (int i = 0; i < 6; ++i) {
        v[i] = *(const float4*)(xr + lane*4 + i*128);
        sum += (v[i].x + v[i].y) + (v[i].z + v[i].w);
    }
    #pragma unroll
    for (int off = 16; off > 0; off >>= 1) sum += __shfl_xor_sync(0xffffffffu, sum, off);
    const float mu = sum * (1.0f/768.0f);
    float var = 0.f;
    #pragma unroll
    for (int i = 0; i < 6; ++i) {
        float dx;
        dx = v[i].x - mu; var += dx*dx;  dx = v[i].y - mu; var += dx*dx;
        dx = v[i].z - mu; var += dx*dx;  dx = v[i].w - mu; var += dx*dx;
    }
    #pragma unroll
    for (int off = 16; off > 0; off >>= 1) var += __shfl_xor_sync(0xffffffffu, var, off);
    const float rstd = rsqrtf(var * (1.0f/768.0f) + 1e-5f);

    #pragma unroll
    for (int i = 0; i < 6; ++i) {
        const int col = lane*4 + i*128;
        const float4 gg = *(const float4*)(g  + col);
        const float4 bb = *(const float4*)(bt + col);
        float r0 = (v[i].x - mu)*rstd*gg.x + bb.x;
        float r1 = (v[i].y - mu)*rstd*gg.y + bb.y;
        float r2 = (v[i].z - mu)*rstd*gg.z + bb.z;
        float r3 = (v[i].w - mu)*rstd*gg.w + bb.w;
        __nv_bfloat16 h0,l0,h1,l1,h2,l2,h3,l3;
        split2(r0,h0,l0); split2(r1,h1,l1); split2(r2,h2,l2); split2(r3,h3,l3);
        const size_t o = (size_t)row * CC + col;
        *(uint2*)(oh + o) = make_uint2(packbf2(h0,h1), packbf2(h2,h3));
        *(uint2*)(ol + o) = make_uint2(packbf2(l0,l1), packbf2(l2,l3));
    }
}

// ================= split-bf16 HMMA GEMM, 3-stage cp.async pipeline =================
// D[M,N] = (Ah+Al)[M,K] @ (Bh+Bl)^T + bias, epilogues:
// EPI 1 = bias+gelu -> bf16 hi/lo; EPI 2 = bias+res -> fp32; EPI 3 = qkv split per-head
#define TEN_BYTES 18432              // 128 rows * 72 elems * 2B
#define STAGE_BYTES (4*TEN_BYTES)    // 73728
#define GEMM_SMEM (3*STAGE_BYTES)    // 221184
#define ROWB 144

template<int EPI>
__global__ __launch_bounds__(256, 1) void hmma_gemm(
    const __nv_bfloat16* __restrict__ Ah, const __nv_bfloat16* __restrict__ Al,
    const __nv_bfloat16* __restrict__ Bh, const __nv_bfloat16* __restrict__ Bl,
    const float* __restrict__ bias, const float* __restrict__ res,
    float* __restrict__ outF, __nv_bfloat16* __restrict__ outH, __nv_bfloat16* __restrict__ outL,
    __nv_bfloat16* __restrict__ okh, __nv_bfloat16* __restrict__ okl,
    __nv_bfloat16* __restrict__ ovh, __nv_bfloat16* __restrict__ ovl,
    int M, int N, int K)
{
    extern __shared__ __align__(1024) char smem[];
    const uint32_t sb = smem_u32(smem);

    const int t    = threadIdx.x;
    const int lane = t & 31;
    const int wid  = t >> 5;
    const int warp_m = wid >> 2;
    const int warp_n = wid & 3;
    const int n0 = blockIdx.x * 128;
    const int m0 = blockIdx.y * 128;

    float acc[4][4][4];
    #pragma unroll
    for (int i = 0; i < 4; ++i)
        #pragma unroll
        for (int j = 0; j < 4; ++j)
            #pragma unroll
            for (int e = 0; e < 4; ++e) acc[i][j][e] = 0.f;

    const uint32_t aBaseH = sb + 0*TEN_BYTES + (uint32_t)(warp_m*64 + (lane & 15)) * ROWB + (lane >> 4) * 16;
    const uint32_t aBaseL = aBaseH + TEN_BYTES;
    const uint32_t bBaseH = sb + 2*TEN_BYTES + (uint32_t)(warp_n*32 + (lane & 7)) * ROWB + ((lane >> 3) & 1) * 16;
    const uint32_t bBaseL = bBaseH + TEN_BYTES;

    const int nch = K >> 6;

    auto load_stage = [&](int buf, int k0) {
        const uint32_t dst = sb + buf * STAGE_BYTES;
        #pragma unroll
        for (int i = 0; i < 4; ++i) {
            const int idx = i * 256 + t;
            const int row = idx >> 3;
            const int seg = idx & 7;
            const uint32_t so = (uint32_t)row * ROWB + seg * 16;
            const size_t ga = (size_t)(m0 + row) * K + k0 + seg * 8;
            const size_t gb = (size_t)(n0 + row) * K + k0 + seg * 8;
            cp16(dst + 0*TEN_BYTES + so, Ah + ga);
            cp16(dst + 1*TEN_BYTES + so, Al + ga);
            cp16(dst + 2*TEN_BYTES + so, Bh + gb);
            cp16(dst + 3*TEN_BYTES + so, Bl + gb);
        }
    };

    load_stage(0, 0);
    CP_COMMIT();
    load_stage(1, 64);
    CP_COMMIT();

    int buf = 0;
    for (int ch = 0; ch < nch; ++ch) {
        if (ch == nch - 1) { CP_WAIT0(); } else { CP_WAIT1(); }
        __syncthreads();
        if (ch + 2 < nch) {
            int nb = buf + 2; if (nb >= 3) nb -= 3;
            load_stage(nb, (ch + 2) << 6);
            CP_COMMIT();
        }

        const uint32_t st = (uint32_t)buf * STAGE_BYTES;
        #pragma unroll
        for (int ks = 0; ks < 4; ++ks) {
            const uint32_t kb = ks * 32;
            uint32_t ahf[4][4], alf[4][4];
            #pragma unroll
            for (int fm = 0; fm < 4; ++fm) {
                ldm_x4(ahf[fm], aBaseH + st + fm * (16 * ROWB) + kb);
                ldm_x4(alf[fm], aBaseL + st + fm * (16 * ROWB) + kb);
            }
            uint32_t bhf[4][2], blf[4][2];
            #pragma unroll
            for (int fn = 0; fn < 4; ++fn) {
                ldm_x2(bhf[fn], bBaseH + st + fn * (8 * ROWB) + kb);
                ldm_x2(blf[fn], bBaseL + st + fn * (8 * ROWB) + kb);
            }
            #pragma unroll
            for (int fm = 0; fm < 4; ++fm)
                #pragma unroll
                for (int fn = 0; fn < 4; ++fn) {
                    mma_bf16(acc[fm][fn], ahf[fm], bhf[fn]);
                    mma_bf16(acc[fm][fn], ahf[fm], blf[fn]);
                    mma_bf16(acc[fm][fn], alf[fm], bhf[fn]);
                }
        }
        ++buf; if (buf >= 3) buf -= 3;
    }

    #pragma unroll
    for (int fm = 0; fm < 4; ++fm) {
        const int row0 = m0 + warp_m*64 + fm*16 + (lane >> 2);
        #pragma unroll
        for (int fn = 0; fn < 4; ++fn) {
            const int col = n0 + warp_n*32 + fn*8 + (lane & 3)*2;
            const float b0 = bias[col], b1 = bias[col + 1];
            float v0 = acc[fm][fn][0] + b0;
            float v1 = acc[fm][fn][1] + b1;
            float v2 = acc[fm][fn][2] + b0;
            float v3 = acc[fm][fn][3] + b1;
            if (EPI == 2) {
                const float2 r0 = *(const float2*)(res + (size_t)row0 * N + col);
                const float2 r1 = *(const float2*)(res + (size_t)(row0 + 8) * N + col);
                v0 += r0.x; v1 += r0.y; v2 += r1.x; v3 += r1.y;
                *(float2*)(outF + (size_t)row0 * N + col)       = make_float2(v0, v1);
                *(float2*)(outF + (size_t)(row0 + 8) * N + col) = make_float2(v2, v3);
            }
            if (EPI == 1) {
                v0 = gelu_tanh(v0); v1 = gelu_tanh(v1);
                v2 = gelu_tanh(v2); v3 = gelu_tanh(v3);
                __nv_bfloat16 h0,l0,h1,l1,h2,l2,h3,l3;
                split2(v0,h0,l0); split2(v1,h1,l1); split2(v2,h2,l2); split2(v3,h3,l3);
                *(uint32_t*)(outH + (size_t)row0 * N + col)       = packbf2(h0,h1);
                *(uint32_t*)(outL + (size_t)row0 * N + col)       = packbf2(l0,l1);
                *(uint32_t*)(outH + (size_t)(row0 + 8) * N + col) = packbf2(h2,h3);
                *(uint32_t*)(outL + (size_t)(row0 + 8) * N + col) = packbf2(l2,l3);
            }
            if (EPI == 3) {
                // qkv: write per-head split, Q pre-scaled by QSCALE
                const int which = col / CC;
                const int cc = col - which * CC;
                const int hh = cc >> 6, d = cc & 63;
                const float sc = (which == 0) ? QSCALE : 1.0f;
                v0 *= sc; v1 *= sc; v2 *= sc; v3 *= sc;
                __nv_bfloat16* oh = (which == 0) ? outH : (which == 1) ? okh : ovh;
                __nv_bfloat16* ol = (which == 0) ? outL : (which == 1) ? okl : ovl;
                const int b0r = row0 >> 11, t0r = row0 & 2047;
                const int b1r = (row0 + 8) >> 11, t1r = (row0 + 8) & 2047;
                const size_t base0 = ((size_t)(b0r * HH + hh) * TT + t0r) * 64 + d;
                const size_t base1 = ((size_t)(b1r * HH + hh) * TT + t1r) * 64 + d;
                __nv_bfloat16 h0,l0,h1,l1;
                split2(v0,h0,l0); split2(v1,h1,l1);
                *(uint32_t*)(oh + base0) = packbf2(h0,h1);
                *(uint32_t*)(ol + base0) = packbf2(l0,l1);
                split2(v2,h0,l0); split2(v3,h1,l1);
                *(uint32_t*)(oh + base1) = packbf2(h0,h1);
                *(uint32_t*)(ol + base1) = packbf2(l0,l1);
            }
        }
    }
}

// ================= split-bf16 HMMA flash attention, 3-stage KV pipeline =================
// Q-tile 128 rows (8 warps x m16), K-tile 64, per-head layout [bh][T][64].
// smem: Qh 16K | Ql 16K | 3 KV stages of (Kh 8K | Kl 8K | Vh 8K | Vl 8K)
#define ATT_SMEM 131072
__global__ __launch_bounds__(256, 1) void attn_mma(
    const __nv_bfloat16* __restrict__ qh, const __nv_bfloat16* __restrict__ ql,
    const __nv_bfloat16* __restrict__ kh, const __nv_bfloat16* __restrict__ kl,
    const __nv_bfloat16* __restrict__ vh, const __nv_bfloat16* __restrict__ vl,
    __nv_bfloat16* __restrict__ yh, __nv_bfloat16* __restrict__ yl)
{
    extern __shared__ __align__(1024) char smem[];
    const uint32_t sb = smem_u32(smem);
    enum { QH_O = 0, QL_O = 16384, KV0 = 32768, KV_STRIDE = 32768,
           KH_O = 0, KL_O = 8192, VH_O = 16384, VL_O = 24576 };

    const int t = threadIdx.x, lane = t & 31, wid = t >> 5;
    const int qt = (int)(gridDim.x - 1) - (int)blockIdx.x;   // big tiles first
    const int bh = blockIdx.y;
    const int qbase = qt * 128;
    const size_t hb = (size_t)bh * TT * 64;
    const int warpQ = wid * 16;

    // Q copy (part of cp.async group 0)
    #pragma unroll
    for (int i = 0; i < 4; ++i) {
        const int idx = t + i * 256;
        const int row = idx >> 3, seg = idx & 7;
        const uint32_t so = SMEM_SWIZZLE_128B((uint32_t)(row * 128 + seg * 16));
        const size_t g = hb + (size_t)(qbase + row) * 64 + seg * 8;
        cp16(sb + QH_O + so, qh + g);
        cp16(sb + QL_O + so, ql + g);
    }
    auto load_kv = [&](int buf, int kt) {
        const uint32_t dst = sb + KV0 + buf * KV_STRIDE;
        #pragma unroll
        for (int i = 0; i < 2; ++i) {
            const int idx = t + i * 256;
            const int row = idx >> 3, seg = idx & 7;
            const uint32_t so = SMEM_SWIZZLE_128B((uint32_t)(row * 128 + seg * 16));
            const size_t g = hb + (size_t)(kt * 64 + row) * 64 + seg * 8;
            cp16(dst + KH_O + so, kh + g);
            cp16(dst + KL_O + so, kl + g);
            cp16(dst + VH_O + so, vh + g);
            cp16(dst + VL_O + so, vl + g);
        }
    };
    const int nkt = 2 * qt + 2;
    load_kv(0, 0);
    CP_COMMIT();
    load_kv(1, 1);
    CP_COMMIT();

    uint32_t qah[4][4], qal[4][4];
    float o[8][4];
    #pragma unroll
    for (int j = 0; j < 8; ++j)
        #pragma unroll
        for (int e = 0; e < 4; ++e) o[j][e] = 0.f;
    float m0r = -1e30f, m1r = -1e30f, l0r = 0.f, l1r = 0.f;

    int buf = 0;
    for (int kt = 0; kt < nkt; ++kt) {
        if (kt == nkt - 1) { CP_WAIT0(); } else { CP_WAIT1(); }
        __syncthreads();
        if (kt + 2 < nkt) {
            int nb = buf + 2; if (nb >= 3) nb -= 3;
            load_kv(nb, kt + 2);
            CP_COMMIT();
        }

        if (kt == 0) {
            const uint32_t qrow = (uint32_t)(warpQ + (lane & 15));
            const uint32_t qbyt = (uint32_t)((lane >> 4) * 16);
            #pragma unroll
            for (int s = 0; s < 4; ++s) {
                const uint32_t so = SMEM_SWIZZLE_128B(qrow * 128 + s * 32 + qbyt);
                ldm_x4(qah[s], sb + QH_O + so);
                ldm_x4(qal[s], sb + QL_O + so);
            }
        }
        const uint32_t st = sb + KV0 + buf * KV_STRIDE;

        // ---- S = Q K^T (3-term split; log2 domain via pre-scaled Q) ----
        float sacc[8][4];
        #pragma unroll
        for (int j = 0; j < 8; ++j) { sacc[j][0]=0.f; sacc[j][1]=0.f; sacc[j][2]=0.f; sacc[j][3]=0.f; }
        #pragma unroll
        for (int j = 0; j < 8; ++j) {
            const uint32_t krow = (uint32_t)(j * 8 + (lane & 7));
            const uint32_t kbyt = (uint32_t)(((lane >> 3) & 3) * 16);
            const uint32_t so0 = SMEM_SWIZZLE_128B(krow * 128 + kbyt);
            const uint32_t so1 = SMEM_SWIZZLE_128B(krow * 128 + 64 + kbyt);
            uint32_t kbh0[4], kbh1[4], kbl0[4], kbl1[4];
            ldm_x4(kbh0, st + KH_O + so0);
            ldm_x4(kbh1, st + KH_O + so1);
            ldm_x4(kbl0, st + KL_O + so0);
            ldm_x4(kbl1, st + KL_O + so1);
            mma_bf16(sacc[j], qah[0], kbh0 + 0); mma_bf16(sacc[j], qah[1], kbh0 + 2);
            mma_bf16(sacc[j], qah[2], kbh1 + 0); mma_bf16(sacc[j], qah[3], kbh1 + 2);
            mma_bf16(sacc[j], qah[0], kbl0 + 0); mma_bf16(sacc[j], qah[1], kbl0 + 2);
            mma_bf16(sacc[j], qah[2], kbl1 + 0); mma_bf16(sacc[j], qah[3], kbl1 + 2);
            mma_bf16(sacc[j], qal[0], kbh0 + 0); mma_bf16(sacc[j], qal[1], kbh0 + 2);
            mma_bf16(sacc[j], qal[2], kbh1 + 0); mma_bf16(sacc[j], qal[3], kbh1 + 2);
        }

        // ---- causal mask (last two K-tiles only) ----
        if (kt >= 2 * qt) {
            const int r0 = qbase + warpQ + (lane >> 2);
            #pragma unroll
            for (int j = 0; j < 8; ++j) {
                const int c = kt * 64 + j * 8 + (lane & 3) * 2;
                if (c     > r0)     sacc[j][0] = -1e30f;
                if (c + 1 > r0)     sacc[j][1] = -1e30f;
                if (c     > r0 + 8) sacc[j][2] = -1e30f;
                if (c + 1 > r0 + 8) sacc[j][3] = -1e30f;
            }
        }

        // ---- online softmax (base-2) ----
        float tm0 = -1e30f, tm1 = -1e30f;
        #pragma unroll
        for (int j = 0; j < 8; ++j) {
            tm0 = fmaxf(tm0, fmaxf(sacc[j][0], sacc[j][1]));
            tm1 = fmaxf(tm1, fmaxf(sacc[j][2], sacc[j][3]));
        }
        tm0 = fmaxf(tm0, __shfl_xor_sync(0xffffffffu, tm0, 1));
        tm0 = fmaxf(tm0, __shfl_xor_sync(0xffffffffu, tm0, 2));
        tm1 = fmaxf(tm1, __shfl_xor_sync(0xffffffffu, tm1, 1));
        tm1 = fmaxf(tm1, __shfl_xor_sync(0xffffffffu, tm1, 2));
        const float mn0 = fmaxf(m0r, tm0), mn1 = fmaxf(m1r, tm1);
        const float al0 = exp2f(m0r - mn0), al1 = exp2f(m1r - mn1);
        m0r = mn0; m1r = mn1;
        float rs0 = 0.f, rs1 = 0.f;
        #pragma unroll
        for (int j = 0; j < 8; ++j) {
            sacc[j][0] = exp2f(sacc[j][0] - mn0);
            sacc[j][1] = exp2f(sacc[j][1] - mn0);
            sacc[j][2] = exp2f(sacc[j][2] - mn1);
            sacc[j][3] = exp2f(sacc[j][3] - mn1);
            rs0 += sacc[j][0] + sacc[j][1];
            rs1 += sacc[j][2] + sacc[j][3];
        }
        rs0 += __shfl_xor_sync(0xffffffffu, rs0, 1);
        rs0 += __shfl_xor_sync(0xffffffffu, rs0, 2);
        rs1 += __shfl_xor_sync(0xffffffffu, rs1, 1);
        rs1 += __shfl_xor_sync(0xffffffffu, rs1, 2);
        l0r = l0r * al0 + rs0;
        l1r = l1r * al1 + rs1;
        #pragma unroll
        for (int j = 0; j < 8; ++j) {
            o[j][0] *= al0; o[j][1] *= al0; o[j][2] *= al1; o[j][3] *= al1;
        }

        // ---- P -> split A-operand fragments (direct re-pack) ----
        uint32_t pah[4][4], pal[4][4];
        #pragma unroll
        for (int s = 0; s < 4; ++s) {
            __nv_bfloat16 h0, l0, h1, l1;
            split2(sacc[2*s][0], h0, l0);   split2(sacc[2*s][1], h1, l1);
            pah[s][0] = packbf2(h0, h1);    pal[s][0] = packbf2(l0, l1);
            split2(sacc[2*s][2], h0, l0);   split2(sacc[2*s][3], h1, l1);
            pah[s][1] = packbf2(h0, h1);    pal[s][1] = packbf2(l0, l1);
            split2(sacc[2*s+1][0], h0, l0); split2(sacc[2*s+1][1], h1, l1);
            pah[s][2] = packbf2(h0, h1);    pal[s][2] = packbf2(l0, l1);
            split2(sacc[2*s+1][2], h0, l0); split2(sacc[2*s+1][3], h1, l1);
            pah[s][3] = packbf2(h0, h1);    pal[s][3] = packbf2(l0, l1);
        }

        // ---- O += P V (3-term split, V^T via ldmatrix.trans) ----
        #pragma unroll
        for (int jp = 0; jp < 4; ++jp) {
            #pragma unroll
            for (int s = 0; s < 4; ++s) {
                const uint32_t vrow = (uint32_t)(s * 16 + (lane & 15));
                const uint32_t vbyt = (uint32_t)(jp * 32 + (lane >> 4) * 16);
                const uint32_t so = SMEM_SWIZZLE_128B(vrow * 128 + vbyt);
                uint32_t vbh[4], vbl[4];
                ldm_x4_trans(vbh, st + VH_O + so);
                ldm_x4_trans(vbl, st + VL_O + so);
                mma_bf16(o[2*jp],     pah[s], vbh + 0);
                mma_bf16(o[2*jp + 1], pah[s], vbh + 2);
                mma_bf16(o[2*jp],     pah[s], vbl + 0);
                mma_bf16(o[2*jp + 1], pah[s], vbl + 2);
                mma_bf16(o[2*jp],     pal[s], vbh + 0);
                mma_bf16(o[2*jp + 1], pal[s], vbh + 2);
            }
        }
        ++buf; if (buf >= 3) buf -= 3;
    }

    // ---- epilogue: normalize, split, write y ----
    const float inv0 = 1.0f / l0r, inv1 = 1.0f / l1r;
    const int b = bh / HH, h = bh - b * HH;
    const size_t row0 = (size_t)b * TT + qbase + warpQ + (lane >> 2);
    #pragma unroll
    for (int j = 0; j < 8; ++j) {
        const int col = h * 64 + j * 8 + (lane & 3) * 2;
        __nv_bfloat16 h0, l0, h1, l1;
        split2(o[j][0] * inv0, h0, l0); split2(o[j][1] * inv0, h1, l1);
        *(uint32_t*)(yh + row0 * CC + col) = packbf2(h0, h1);
        *(uint32_t*)(yl + row0 * CC + col) = packbf2(l0, l1);
        split2(o[j][2] * inv1, h0, l0); split2(o[j][3] * inv1, h1, l1);
        *(uint32_t*)(yh + (row0 + 8) * CC + col) = packbf2(h0, h1);
        *(uint32_t*)(yl + (row0 + 8) * CC + col) = packbf2(l0, l1);
    }
}

// ================= launch =================
extern "C" void kernel_launch(void* const* d_in, const int* in_sizes, int n_in,
                              void* d_out, int out_size)
{
    const float* x       = (const float*)d_in[0];
    const float* ln1_g   = (const float*)d_in[1];
    const float* ln1_b   = (const float*)d_in[2];
    const float* w_attn  = (const float*)d_in[3];
    const float* b_attn  = (const float*)d_in[4];
    const float* w_aproj = (const float*)d_in[5];
    const float* b_aproj = (const float*)d_in[6];
    const float* ln2_g   = (const float*)d_in[7];
    const float* ln2_b   = (const float*)d_in[8];
    const float* w_fc    = (const float*)d_in[9];
    const float* b_fc    = (const float*)d_in[10];
    const float* w_mproj = (const float*)d_in[11];
    const float* b_mproj = (const float*)d_in[12];
    float* out = (float*)d_out;

    __nv_bfloat16 *h1h,*h1l,*yh,*yl,*h2h,*h2l,*fch,*fcl;
    __nv_bfloat16 *wqh,*wql,*wah,*wal,*wfh,*wfl,*wmh,*wml;
    __nv_bfloat16 *qsh,*qsl,*ksh,*ksl,*vsh,*vsl;
    float *x1;
    cudaGetSymbolAddress((void**)&h1h, g_h1h); cudaGetSymbolAddress((void**)&h1l, g_h1l);
    cudaGetSymbolAddress((void**)&yh,  g_yh);  cudaGetSymbolAddress((void**)&yl,  g_yl);
    cudaGetSymbolAddress((void**)&x1,  g_x1);
    cudaGetSymbolAddress((void**)&h2h, g_h2h); cudaGetSymbolAddress((void**)&h2l, g_h2l);
    cudaGetSymbolAddress((void**)&fch, g_fch); cudaGetSymbolAddress((void**)&fcl, g_fcl);
    cudaGetSymbolAddress((void**)&wqh, g_wqh); cudaGetSymbolAddress((void**)&wql, g_wql);
    cudaGetSymbolAddress((void**)&wah, g_wah); cudaGetSymbolAddress((void**)&wal, g_wal);
    cudaGetSymbolAddress((void**)&wfh, g_wfh); cudaGetSymbolAddress((void**)&wfl, g_wfl);
    cudaGetSymbolAddress((void**)&wmh, g_wmh); cudaGetSymbolAddress((void**)&wml, g_wml);
    cudaGetSymbolAddress((void**)&qsh, g_qsh); cudaGetSymbolAddress((void**)&qsl, g_qsl);
    cudaGetSymbolAddress((void**)&ksh, g_ksh); cudaGetSymbolAddress((void**)&ksl, g_ksl);
    cudaGetSymbolAddress((void**)&vsh, g_vsh); cudaGetSymbolAddress((void**)&vsl, g_vsl);

    cudaFuncSetAttribute(hmma_gemm<1>, cudaFuncAttributeMaxDynamicSharedMemorySize, GEMM_SMEM);
    cudaFuncSetAttribute(hmma_gemm<2>, cudaFuncAttributeMaxDynamicSharedMemorySize, GEMM_SMEM);
    cudaFuncSetAttribute(hmma_gemm<3>, cudaFuncAttributeMaxDynamicSharedMemorySize, GEMM_SMEM);
    cudaFuncSetAttribute(attn_mma,     cudaFuncAttributeMaxDynamicSharedMemorySize, ATT_SMEM);

    // weight transpose + split
    tsplit_kernel<<<dim3(QKVC/32, CC/32),  dim3(256)>>>(w_attn,  wqh, wql, CC,  QKVC);
    tsplit_kernel<<<dim3(CC/32,   CC/32),  dim3(256)>>>(w_aproj, wah, wal, CC,  CC);
    tsplit_kernel<<<dim3(FFC/32,  CC/32),  dim3(256)>>>(w_fc,    wfh, wfl, CC,  FFC);
    tsplit_kernel<<<dim3(CC/32,   FFC/32), dim3(256)>>>(w_mproj, wmh, wml, FFC, CC);

    // 1) h1 = ln1(x)  (split)
    ln_split_kernel<<<NROWS/8, 256>>>(x, ln1_g, ln1_b, h1h, h1l);
    // 2) q/k/v = split-per-head(h1 @ w_attn + b_attn), Q scaled (fused epilogue)
    hmma_gemm<3><<<dim3(QKVC/128, NROWS/128), 256, GEMM_SMEM>>>(
        h1h, h1l, wqh, wql, b_attn, nullptr, nullptr,
        qsh, qsl, ksh, ksl, vsh, vsl, NROWS, QKVC, CC);
    // 3) y = attention (HMMA flash, base-2 softmax)
    attn_mma<<<dim3(TT/128, BB*HH), 256, ATT_SMEM>>>(qsh, qsl, ksh, ksl, vsh, vsl, yh, yl);
    // 4) x1 = y @ w_aproj + b_aproj + x
    hmma_gemm<2><<<dim3(CC/128, NROWS/128), 256, GEMM_SMEM>>>(
        yh, yl, wah, wal, b_aproj, x, x1, nullptr, nullptr,
        nullptr, nullptr, nullptr, nullptr, NROWS, CC, CC);
    // 5) h2 = ln2(x1)  (split)
    ln_split_kernel<<<NROWS/8, 256>>>(x1, ln2_g, ln2_b, h2h, h2l);
    // 6) fc = gelu(h2 @ w_fc + b_fc)  (split)
    hmma_gemm<1><<<dim3(FFC/128, NROWS/128), 256, GEMM_SMEM>>>(
        h2h, h2l, wfh, wfl, b_fc, nullptr, nullptr, fch, fcl,
        nullptr, nullptr, nullptr, nullptr, NROWS, FFC, CC);
    // 7) out = fc @ w_mproj + b_mproj + x1
    hmma_gemm<2><<<dim3(CC/128, NROWS/128), 256, GEMM_SMEM>>>(
        fch, fcl, wmh, wml, b_mproj, x1, out, nullptr, nullptr,
        nullptr, nullptr, nullptr, nullptr, NROWS, CC, FFC);
}

// round 6
// speedup vs baseline: 3.7145x; 1.3905x over previous
#include <cuda_runtime.h>
#include <cuda_fp16.h>
#include <math.h>
#include <stdint.h>

// Problem constants
#define BB 4
#define TT 2048
#define CC 768
#define HH 12
#define DD 64
#define NROWS (BB*TT)          // 8192
#define QKVC (3*CC)            // 2304
#define FFC (4*CC)             // 3072

#define QSCALE (0.125f * 1.4426950408889634f)   // 1/sqrt(D) * log2(e)

// ================= scratch (allocation-free: __device__ globals) =================
__device__ __half g_h1[NROWS*CC];
__device__ __half g_y [NROWS*CC];
__device__ float  g_x1[NROWS*CC];
__device__ __half g_h2[NROWS*CC];
__device__ __half g_fc[NROWS*FFC];
__device__ __half g_wqh[QKVC*CC], g_wql[QKVC*CC];   // [N][K] K-major, hi+lo
__device__ __half g_wah[CC*CC],   g_wal[CC*CC];
__device__ __half g_wfh[FFC*CC],  g_wfl[FFC*CC];
__device__ __half g_wmh[CC*FFC],  g_wml[CC*FFC];
// per-head q/k/v: [b*H+h][T][64]; Q split hi/lo, K/V single
__device__ __half g_qsh[NROWS*CC], g_qsl[NROWS*CC];
__device__ __half g_ks [NROWS*CC];
__device__ __half g_vs [NROWS*CC];

__device__ __forceinline__ void split2h(float v, __half& h, __half& l) {
    h = __float2half_rn(v);
    l = __float2half_rn(v - __half2float(h));
}
__device__ __forceinline__ uint32_t packh2(__half a, __half b) {
    return (uint32_t)__half_as_ushort(a) | ((uint32_t)__half_as_ushort(b) << 16);
}
__device__ __forceinline__ uint32_t smem_u32(const void* p) {
    uint32_t a;
    asm("{ .reg .u64 t; cvta.to.shared.u64 t, %1; cvt.u32.u64 %0, t; }" : "=r"(a) : "l"(p));
    return a;
}
__device__ __forceinline__ void cp16(uint32_t saddr, const void* g) {
    asm volatile("cp.async.cg.shared.global [%0], [%1], 16;" :: "r"(saddr), "l"(g));
}
#define CP_COMMIT() asm volatile("cp.async.commit_group;" ::: "memory")
#define CP_WAIT1()  asm volatile("cp.async.wait_group 1;" ::: "memory")
#define CP_WAIT0()  asm volatile("cp.async.wait_group 0;" ::: "memory")

__device__ __forceinline__ void ldm_x4(uint32_t* r, uint32_t addr) {
    asm volatile("ldmatrix.sync.aligned.m8n8.x4.shared.b16 {%0,%1,%2,%3}, [%4];"
        : "=r"(r[0]), "=r"(r[1]), "=r"(r[2]), "=r"(r[3]) : "r"(addr));
}
__device__ __forceinline__ void ldm_x4_trans(uint32_t* r, uint32_t addr) {
    asm volatile("ldmatrix.sync.aligned.m8n8.x4.trans.shared.b16 {%0,%1,%2,%3}, [%4];"
        : "=r"(r[0]), "=r"(r[1]), "=r"(r[2]), "=r"(r[3]) : "r"(addr));
}
__device__ __forceinline__ void ldm_x2(uint32_t* r, uint32_t addr) {
    asm volatile("ldmatrix.sync.aligned.m8n8.x2.shared.b16 {%0,%1}, [%2];"
        : "=r"(r[0]), "=r"(r[1]) : "r"(addr));
}
__device__ __forceinline__ void mma_f16(float* c, const uint32_t* a, const uint32_t* b) {
    asm volatile("mma.sync.aligned.m16n8k16.row.col.f32.f16.f16.f32 "
        "{%0,%1,%2,%3}, {%4,%5,%6,%7}, {%8,%9}, {%0,%1,%2,%3};"
        : "+f"(c[0]), "+f"(c[1]), "+f"(c[2]), "+f"(c[3])
        : "r"(a[0]), "r"(a[1]), "r"(a[2]), "r"(a[3]), "r"(b[0]), "r"(b[1]));
}
#define SMEM_SWIZZLE_128B(o) ((o) ^ (((o) >> 3) & 0x70))

__device__ __forceinline__ float gelu_tanh(float v) {
    const float c = 0.7978845608028654f;
    float u = c * (v + 0.044715f * v * v * v);
    return 0.5f * v * (1.0f + tanhf(u));
}

// ================= weight transpose + split: w[K,N] -> wt_hi/lo[N,K] fp16 =================
__global__ __launch_bounds__(256) void tsplit_kernel(const float* __restrict__ w,
                                                     __half* __restrict__ th,
                                                     __half* __restrict__ tl,
                                                     int K, int N)
{
    __shared__ float tile[32][33];
    const int tx = threadIdx.x & 31, ty = threadIdx.x >> 5;   // 32x8
    const int n0 = blockIdx.x * 32, k0 = blockIdx.y * 32;
    #pragma unroll
    for (int r = 0; r < 4; ++r)
        tile[ty + 8*r][tx] = w[(size_t)(k0 + ty + 8*r) * N + n0 + tx];
    __syncthreads();
    #pragma unroll
    for (int r = 0; r < 4; ++r) {
        const float v = tile[tx][ty + 8*r];
        __half h, l; split2h(v, h, l);
        const size_t o = (size_t)(n0 + ty + 8*r) * K + k0 + tx;
        th[o] = h; tl[o] = l;
    }
}

// ================= LayerNorm -> single fp16 =================
__global__ __launch_bounds__(256) void ln_h_kernel(const float* __restrict__ x,
                                                   const float* __restrict__ g,
                                                   const float* __restrict__ bt,
                                                   __half* __restrict__ oh)
{
    const int row  = blockIdx.x * 8 + (threadIdx.x >> 5);
    const int lane = threadIdx.x & 31;
    const float* xr = x + (size_t)row * CC;

    float4 v[6];
    float sum = 0.f;
    #pragma unroll
    for (int i = 0; i < 6; ++i) {
        v[i] = *(const float4*)(xr + lane*4 + i*128);
        sum += (v[i].x + v[i].y) + (v[i].z + v[i].w);
    }
    #pragma unroll
    for (int off = 16; off > 0; off >>= 1) sum += __shfl_xor_sync(0xffffffffu, sum, off);
    const float mu = sum * (1.0f/768.0f);
    float var = 0.f;
    #pragma unroll
    for (int i = 0; i < 6; ++i) {
        float dx;
        dx = v[i].x - mu; var += dx*dx;  dx = v[i].y - mu; var += dx*dx;
        dx = v[i].z - mu; var += dx*dx;  dx = v[i].w - mu; var += dx*dx;
    }
    #pragma unroll
    for (int off = 16; off > 0; off >>= 1) var += __shfl_xor_sync(0xffffffffu, var, off);
    const float rstd = rsqrtf(var * (1.0f/768.0f) + 1e-5f);

    #pragma unroll
    for (int i = 0; i < 6; ++i) {
        const int col = lane*4 + i*128;
        const float4 gg = *(const float4*)(g  + col);
        const float4 bb = *(const float4*)(bt + col);
        const float r0 = (v[i].x - mu)*rstd*gg.x + bb.x;
        const float r1 = (v[i].y - mu)*rstd*gg.y + bb.y;
        const float r2 = (v[i].z - mu)*rstd*gg.z + bb.z;
        const float r3 = (v[i].w - mu)*rstd*gg.w + bb.w;
        const size_t o = (size_t)row * CC + col;
        *(uint2*)(oh + o) = make_uint2(
            packh2(__float2half_rn(r0), __float2half_rn(r1)),
            packh2(__float2half_rn(r2), __float2half_rn(r3)));
    }
}

// ================= 2-term fp16 HMMA GEMM, 3-stage cp.async pipeline =================
// D[M,N] = A16[M,K] @ (Wh+Wl)^T + bias, epilogues:
// EPI 1 = bias+gelu -> fp16; EPI 2 = bias+res -> fp32; EPI 3 = qkv per-head (Q split, K/V single)
#define TEN_BYTES 18432              // 128 rows * 72 elems * 2B
#define STAGE_BYTES (3*TEN_BYTES)    // A, Bh, Bl  = 55296
#define GEMM_SMEM (3*STAGE_BYTES)    // 165888
#define ROWB 144

template<int EPI>
__global__ __launch_bounds__(256, 1) void hmma_gemm(
    const __half* __restrict__ Aa,
    const __half* __restrict__ Bh, const __half* __restrict__ Bl,
    const float* __restrict__ bias, const float* __restrict__ res,
    float* __restrict__ outF, __half* __restrict__ outH, __half* __restrict__ outL,
    __half* __restrict__ oks, __half* __restrict__ ovs,
    int M, int N, int K)
{
    extern __shared__ __align__(1024) char smem[];
    const uint32_t sb = smem_u32(smem);

    const int t    = threadIdx.x;
    const int lane = t & 31;
    const int wid  = t >> 5;
    const int warp_m = wid >> 2;
    const int warp_n = wid & 3;
    const int n0 = blockIdx.x * 128;
    const int m0 = blockIdx.y * 128;

    float acc[4][4][4];
    #pragma unroll
    for (int i = 0; i < 4; ++i)
        #pragma unroll
        for (int j = 0; j < 4; ++j)
            #pragma unroll
            for (int e = 0; e < 4; ++e) acc[i][j][e] = 0.f;

    const uint32_t aBase  = sb + 0*TEN_BYTES + (uint32_t)(warp_m*64 + (lane & 15)) * ROWB + (lane >> 4) * 16;
    const uint32_t bBaseH = sb + 1*TEN_BYTES + (uint32_t)(warp_n*32 + (lane & 7)) * ROWB + ((lane >> 3) & 1) * 16;
    const uint32_t bBaseL = bBaseH + TEN_BYTES;

    const int nch = K >> 6;

    auto load_stage = [&](int buf, int k0) {
        const uint32_t dst = sb + buf * STAGE_BYTES;
        #pragma unroll
        for (int i = 0; i < 4; ++i) {
            const int idx = i * 256 + t;
            const int row = idx >> 3;
            const int seg = idx & 7;
            const uint32_t so = (uint32_t)row * ROWB + seg * 16;
            const size_t ga = (size_t)(m0 + row) * K + k0 + seg * 8;
            const size_t gb = (size_t)(n0 + row) * K + k0 + seg * 8;
            cp16(dst + 0*TEN_BYTES + so, Aa + ga);
            cp16(dst + 1*TEN_BYTES + so, Bh + gb);
            cp16(dst + 2*TEN_BYTES + so, Bl + gb);
        }
    };

    load_stage(0, 0);
    CP_COMMIT();
    load_stage(1, 64);
    CP_COMMIT();

    int buf = 0;
    for (int ch = 0; ch < nch; ++ch) {
        if (ch == nch - 1) { CP_WAIT0(); } else { CP_WAIT1(); }
        __syncthreads();
        if (ch + 2 < nch) {
            int nb = buf + 2; if (nb >= 3) nb -= 3;
            load_stage(nb, (ch + 2) << 6);
            CP_COMMIT();
        }

        const uint32_t st = (uint32_t)buf * STAGE_BYTES;
        #pragma unroll
        for (int ks = 0; ks < 4; ++ks) {
            const uint32_t kb = ks * 32;
            uint32_t af[4][4];
            #pragma unroll
            for (int fm = 0; fm < 4; ++fm)
                ldm_x4(af[fm], aBase + st + fm * (16 * ROWB) + kb);
            uint32_t bhf[4][2], blf[4][2];
            #pragma unroll
            for (int fn = 0; fn < 4; ++fn) {
                ldm_x2(bhf[fn], bBaseH + st + fn * (8 * ROWB) + kb);
                ldm_x2(blf[fn], bBaseL + st + fn * (8 * ROWB) + kb);
            }
            #pragma unroll
            for (int fm = 0; fm < 4; ++fm)
                #pragma unroll
                for (int fn = 0; fn < 4; ++fn) {
                    mma_f16(acc[fm][fn], af[fm], bhf[fn]);
                    mma_f16(acc[fm][fn], af[fm], blf[fn]);
                }
        }
        ++buf; if (buf >= 3) buf -= 3;
    }

    #pragma unroll
    for (int fm = 0; fm < 4; ++fm) {
        const int row0 = m0 + warp_m*64 + fm*16 + (lane >> 2);
        #pragma unroll
        for (int fn = 0; fn < 4; ++fn) {
            const int col = n0 + warp_n*32 + fn*8 + (lane & 3)*2;
            const float b0 = bias[col], b1 = bias[col + 1];
            float v0 = acc[fm][fn][0] + b0;
            float v1 = acc[fm][fn][1] + b1;
            float v2 = acc[fm][fn][2] + b0;
            float v3 = acc[fm][fn][3] + b1;
            if (EPI == 2) {
                const float2 r0 = *(const float2*)(res + (size_t)row0 * N + col);
                const float2 r1 = *(const float2*)(res + (size_t)(row0 + 8) * N + col);
                v0 += r0.x; v1 += r0.y; v2 += r1.x; v3 += r1.y;
                *(float2*)(outF + (size_t)row0 * N + col)       = make_float2(v0, v1);
                *(float2*)(outF + (size_t)(row0 + 8) * N + col) = make_float2(v2, v3);
            }
            if (EPI == 1) {
                v0 = gelu_tanh(v0); v1 = gelu_tanh(v1);
                v2 = gelu_tanh(v2); v3 = gelu_tanh(v3);
                *(uint32_t*)(outH + (size_t)row0 * N + col) =
                    packh2(__float2half_rn(v0), __float2half_rn(v1));
                *(uint32_t*)(outH + (size_t)(row0 + 8) * N + col) =
                    packh2(__float2half_rn(v2), __float2half_rn(v3));
            }
            if (EPI == 3) {
                const int which = col / CC;
                const int cc = col - which * CC;
                const int hh = cc >> 6, d = cc & 63;
                const int b0r = row0 >> 11, t0r = row0 & 2047;
                const int b1r = (row0 + 8) >> 11, t1r = (row0 + 8) & 2047;
                const size_t base0 = ((size_t)(b0r * HH + hh) * TT + t0r) * 64 + d;
                const size_t base1 = ((size_t)(b1r * HH + hh) * TT + t1r) * 64 + d;
                if (which == 0) {
                    v0 *= QSCALE; v1 *= QSCALE; v2 *= QSCALE; v3 *= QSCALE;
                    __half h0,l0,h1,l1;
                    split2h(v0,h0,l0); split2h(v1,h1,l1);
                    *(uint32_t*)(outH + base0) = packh2(h0,h1);
                    *(uint32_t*)(outL + base0) = packh2(l0,l1);
                    split2h(v2,h0,l0); split2h(v3,h1,l1);
                    *(uint32_t*)(outH + base1) = packh2(h0,h1);
                    *(uint32_t*)(outL + base1) = packh2(l0,l1);
                } else {
                    __half* o = (which == 1) ? oks : ovs;
                    *(uint32_t*)(o + base0) = packh2(__float2half_rn(v0), __float2half_rn(v1));
                    *(uint32_t*)(o + base1) = packh2(__float2half_rn(v2), __float2half_rn(v3));
                }
            }
        }
    }
}

// ================= 2-term fp16 HMMA flash attention, 3-stage KV pipeline =================
// Q-tile 128 rows (8 warps x m16), K-tile 64, per-head layout [bh][T][64].
// smem: Qh 16K | Ql 16K | 3 KV stages of (K 8K | V 8K)
#define ATT_SMEM 81920
__global__ __launch_bounds__(256, 1) void attn_mma(
    const __half* __restrict__ qh, const __half* __restrict__ ql,
    const __half* __restrict__ kk, const __half* __restrict__ vv,
    __half* __restrict__ yy)
{
    extern __shared__ __align__(1024) char smem[];
    const uint32_t sb = smem_u32(smem);
    enum { QH_O = 0, QL_O = 16384, KV0 = 32768, KV_STRIDE = 16384,
           K_O = 0, V_O = 8192 };

    const int t = threadIdx.x, lane = t & 31, wid = t >> 5;
    const int qt = (int)(gridDim.x - 1) - (int)blockIdx.x;   // big tiles first
    const int bh = blockIdx.y;
    const int qbase = qt * 128;
    const size_t hb = (size_t)bh * TT * 64;
    const int warpQ = wid * 16;

    // Q copy
    #pragma unroll
    for (int i = 0; i < 4; ++i) {
        const int idx = t + i * 256;
        const int row = idx >> 3, seg = idx & 7;
        const uint32_t so = SMEM_SWIZZLE_128B((uint32_t)(row * 128 + seg * 16));
        const size_t g = hb + (size_t)(qbase + row) * 64 + seg * 8;
        cp16(sb + QH_O + so, qh + g);
        cp16(sb + QL_O + so, ql + g);
    }
    auto load_kv = [&](int buf, int kt) {
        const uint32_t dst = sb + KV0 + buf * KV_STRIDE;
        #pragma unroll
        for (int i = 0; i < 2; ++i) {
            const int idx = t + i * 256;
            const int row = idx >> 3, seg = idx & 7;
            const uint32_t so = SMEM_SWIZZLE_128B((uint32_t)(row * 128 + seg * 16));
            const size_t g = hb + (size_t)(kt * 64 + row) * 64 + seg * 8;
            cp16(dst + K_O + so, kk + g);
            cp16(dst + V_O + so, vv + g);
        }
    };
    const int nkt = 2 * qt + 2;
    load_kv(0, 0);
    CP_COMMIT();
    load_kv(1, 1);
    CP_COMMIT();

    uint32_t qah[4][4], qal[4][4];
    float o[8][4];
    #pragma unroll
    for (int j = 0; j < 8; ++j)
        #pragma unroll
        for (int e = 0; e < 4; ++e) o[j][e] = 0.f;
    float m0r = -1e30f, m1r = -1e30f, l0r = 0.f, l1r = 0.f;

    int buf = 0;
    for (int kt = 0; kt < nkt; ++kt) {
        if (kt == nkt - 1) { CP_WAIT0(); } else { CP_WAIT1(); }
        __syncthreads();
        if (kt + 2 < nkt) {
            int nb = buf + 2; if (nb >= 3) nb -= 3;
            load_kv(nb, kt + 2);
            CP_COMMIT();
        }

        if (kt == 0) {
            const uint32_t qrow = (uint32_t)(warpQ + (lane & 15));
            const uint32_t qbyt = (uint32_t)((lane >> 4) * 16);
            #pragma unroll
            for (int s = 0; s < 4; ++s) {
                const uint32_t so = SMEM_SWIZZLE_128B(qrow * 128 + s * 32 + qbyt);
                ldm_x4(qah[s], sb + QH_O + so);
                ldm_x4(qal[s], sb + QL_O + so);
            }
        }
        const uint32_t st = sb + KV0 + buf * KV_STRIDE;

        // ---- S = (Qh+Ql) K16^T ----
        float sacc[8][4];
        #pragma unroll
        for (int j = 0; j < 8; ++j) { sacc[j][0]=0.f; sacc[j][1]=0.f; sacc[j][2]=0.f; sacc[j][3]=0.f; }
        #pragma unroll
        for (int j = 0; j < 8; ++j) {
            const uint32_t krow = (uint32_t)(j * 8 + (lane & 7));
            const uint32_t kbyt = (uint32_t)(((lane >> 3) & 3) * 16);
            const uint32_t so0 = SMEM_SWIZZLE_128B(krow * 128 + kbyt);
            const uint32_t so1 = SMEM_SWIZZLE_128B(krow * 128 + 64 + kbyt);
            uint32_t kb0[4], kb1[4];
            ldm_x4(kb0, st + K_O + so0);
            ldm_x4(kb1, st + K_O + so1);
            mma_f16(sacc[j], qah[0], kb0 + 0); mma_f16(sacc[j], qah[1], kb0 + 2);
            mma_f16(sacc[j], qah[2], kb1 + 0); mma_f16(sacc[j], qah[3], kb1 + 2);
            mma_f16(sacc[j], qal[0], kb0 + 0); mma_f16(sacc[j], qal[1], kb0 + 2);
            mma_f16(sacc[j], qal[2], kb1 + 0); mma_f16(sacc[j], qal[3], kb1 + 2);
        }

        // ---- causal mask (last two K-tiles only) ----
        if (kt >= 2 * qt) {
            const int r0 = qbase + warpQ + (lane >> 2);
            #pragma unroll
            for (int j = 0; j < 8; ++j) {
                const int c = kt * 64 + j * 8 + (lane & 3) * 2;
                if (c     > r0)     sacc[j][0] = -1e30f;
                if (c + 1 > r0)     sacc[j][1] = -1e30f;
                if (c     > r0 + 8) sacc[j][2] = -1e30f;
                if (c + 1 > r0 + 8) sacc[j][3] = -1e30f;
            }
        }

        // ---- online softmax (base-2) ----
        float tm0 = -1e30f, tm1 = -1e30f;
        #pragma unroll
        for (int j = 0; j < 8; ++j) {
            tm0 = fmaxf(tm0, fmaxf(sacc[j][0], sacc[j][1]));
            tm1 = fmaxf(tm1, fmaxf(sacc[j][2], sacc[j][3]));
        }
        tm0 = fmaxf(tm0, __shfl_xor_sync(0xffffffffu, tm0, 1));
        tm0 = fmaxf(tm0, __shfl_xor_sync(0xffffffffu, tm0, 2));
        tm1 = fmaxf(tm1, __shfl_xor_sync(0xffffffffu, tm1, 1));
        tm1 = fmaxf(tm1, __shfl_xor_sync(0xffffffffu, tm1, 2));
        const float mn0 = fmaxf(m0r, tm0), mn1 = fmaxf(m1r, tm1);
        const float al0 = exp2f(m0r - mn0), al1 = exp2f(m1r - mn1);
        m0r = mn0; m1r = mn1;
        float rs0 = 0.f, rs1 = 0.f;
        #pragma unroll
        for (int j = 0; j < 8; ++j) {
            sacc[j][0] = exp2f(sacc[j][0] - mn0);
            sacc[j][1] = exp2f(sacc[j][1] - mn0);
            sacc[j][2] = exp2f(sacc[j][2] - mn1);
            sacc[j][3] = exp2f(sacc[j][3] - mn1);
            rs0 += sacc[j][0] + sacc[j][1];
            rs1 += sacc[j][2] + sacc[j][3];
        }
        rs0 += __shfl_xor_sync(0xffffffffu, rs0, 1);
        rs0 += __shfl_xor_sync(0xffffffffu, rs0, 2);
        rs1 += __shfl_xor_sync(0xffffffffu, rs1, 1);
        rs1 += __shfl_xor_sync(0xffffffffu, rs1, 2);
        l0r = l0r * al0 + rs0;
        l1r = l1r * al1 + rs1;
        #pragma unroll
        for (int j = 0; j < 8; ++j) {
            o[j][0] *= al0; o[j][1] *= al0; o[j][2] *= al1; o[j][3] *= al1;
        }

        // ---- P -> split fp16 A-operand fragments (from exact fp32 regs) ----
        uint32_t pah[4][4], pal[4][4];
        #pragma unroll
        for (int s = 0; s < 4; ++s) {
            __half h0, l0, h1, l1;
            split2h(sacc[2*s][0], h0, l0);   split2h(sacc[2*s][1], h1, l1);
            pah[s][0] = packh2(h0, h1);      pal[s][0] = packh2(l0, l1);
            split2h(sacc[2*s][2], h0, l0);   split2h(sacc[2*s][3], h1, l1);
            pah[s][1] = packh2(h0, h1);      pal[s][1] = packh2(l0, l1);
            split2h(sacc[2*s+1][0], h0, l0); split2h(sacc[2*s+1][1], h1, l1);
            pah[s][2] = packh2(h0, h1);      pal[s][2] = packh2(l0, l1);
            split2h(sacc[2*s+1][2], h0, l0); split2h(sacc[2*s+1][3], h1, l1);
            pah[s][3] = packh2(h0, h1);      pal[s][3] = packh2(l0, l1);
        }

        // ---- O += (Ph+Pl) V16 (V^T via ldmatrix.trans) ----
        #pragma unroll
        for (int jp = 0; jp < 4; ++jp) {
            #pragma unroll
            for (int s = 0; s < 4; ++s) {
                const uint32_t vrow = (uint32_t)(s * 16 + (lane & 15));
                const uint32_t vbyt = (uint32_t)(jp * 32 + (lane >> 4) * 16);
                const uint32_t so = SMEM_SWIZZLE_128B(vrow * 128 + vbyt);
                uint32_t vb[4];
                ldm_x4_trans(vb, st + V_O + so);
                mma_f16(o[2*jp],     pah[s], vb + 0);
                mma_f16(o[2*jp + 1], pah[s], vb + 2);
                mma_f16(o[2*jp],     pal[s], vb + 0);
                mma_f16(o[2*jp + 1], pal[s], vb + 2);
            }
        }
        ++buf; if (buf >= 3) buf -= 3;
    }

    // ---- epilogue: normalize, write y (single fp16) ----
    const float inv0 = 1.0f / l0r, inv1 = 1.0f / l1r;
    const int b = bh / HH, h = bh - b * HH;
    const size_t row0 = (size_t)b * TT + qbase + warpQ + (lane >> 2);
    #pragma unroll
    for (int j = 0; j < 8; ++j) {
        const int col = h * 64 + j * 8 + (lane & 3) * 2;
        *(uint32_t*)(yy + row0 * CC + col) =
            packh2(__float2half_rn(o[j][0] * inv0), __float2half_rn(o[j][1] * inv0));
        *(uint32_t*)(yy + (row0 + 8) * CC + col) =
            packh2(__float2half_rn(o[j][2] * inv1), __float2half_rn(o[j][3] * inv1));
    }
}

// ================= launch =================
extern "C" void kernel_launch(void* const* d_in, const int* in_sizes, int n_in,
                              void* d_out, int out_size)
{
    const float* x       = (const float*)d_in[0];
    const float* ln1_g   = (const float*)d_in[1];
    const float* ln1_b   = (const float*)d_in[2];
    const float* w_attn  = (const float*)d_in[3];
    const float* b_attn  = (const float*)d_in[4];
    const float* w_aproj = (const float*)d_in[5];
    const float* b_aproj = (const float*)d_in[6];
    const float* ln2_g   = (const float*)d_in[7];
    const float* ln2_b   = (const float*)d_in[8];
    const float* w_fc    = (const float*)d_in[9];
    const float* b_fc    = (const float*)d_in[10];
    const float* w_mproj = (const float*)d_in[11];
    const float* b_mproj = (const float*)d_in[12];
    float* out = (float*)d_out;

    __half *h1,*y,*h2,*fc;
    __half *wqh,*wql,*wah,*wal,*wfh,*wfl,*wmh,*wml;
    __half *qsh,*qsl,*ks,*vs;
    float *x1;
    cudaGetSymbolAddress((void**)&h1,  g_h1);
    cudaGetSymbolAddress((void**)&y,   g_y);
    cudaGetSymbolAddress((void**)&x1,  g_x1);
    cudaGetSymbolAddress((void**)&h2,  g_h2);
    cudaGetSymbolAddress((void**)&fc,  g_fc);
    cudaGetSymbolAddress((void**)&wqh, g_wqh); cudaGetSymbolAddress((void**)&wql, g_wql);
    cudaGetSymbolAddress((void**)&wah, g_wah); cudaGetSymbolAddress((void**)&wal, g_wal);
    cudaGetSymbolAddress((void**)&wfh, g_wfh); cudaGetSymbolAddress((void**)&wfl, g_wfl);
    cudaGetSymbolAddress((void**)&wmh, g_wmh); cudaGetSymbolAddress((void**)&wml, g_wml);
    cudaGetSymbolAddress((void**)&qsh, g_qsh); cudaGetSymbolAddress((void**)&qsl, g_qsl);
    cudaGetSymbolAddress((void**)&ks,  g_ks);  cudaGetSymbolAddress((void**)&vs,  g_vs);

    cudaFuncSetAttribute(hmma_gemm<1>, cudaFuncAttributeMaxDynamicSharedMemorySize, GEMM_SMEM);
    cudaFuncSetAttribute(hmma_gemm<2>, cudaFuncAttributeMaxDynamicSharedMemorySize, GEMM_SMEM);
    cudaFuncSetAttribute(hmma_gemm<3>, cudaFuncAttributeMaxDynamicSharedMemorySize, GEMM_SMEM);
    cudaFuncSetAttribute(attn_mma,     cudaFuncAttributeMaxDynamicSharedMemorySize, ATT_SMEM);

    // weight transpose + split
    tsplit_kernel<<<dim3(QKVC/32, CC/32),  dim3(256)>>>(w_attn,  wqh, wql, CC,  QKVC);
    tsplit_kernel<<<dim3(CC/32,   CC/32),  dim3(256)>>>(w_aproj, wah, wal, CC,  CC);
    tsplit_kernel<<<dim3(FFC/32,  CC/32),  dim3(256)>>>(w_fc,    wfh, wfl, CC,  FFC);
    tsplit_kernel<<<dim3(CC/32,   FFC/32), dim3(256)>>>(w_mproj, wmh, wml, FFC, CC);

    // 1) h1 = ln1(x)  (single fp16)
    ln_h_kernel<<<NROWS/8, 256>>>(x, ln1_g, ln1_b, h1);
    // 2) q/k/v = per-head(h1 @ w_attn + b_attn); Q split+scaled, K/V single
    hmma_gemm<3><<<dim3(QKVC/128, NROWS/128), 256, GEMM_SMEM>>>(
        h1, wqh, wql, b_attn, nullptr, nullptr, qsh, qsl, ks, vs, NROWS, QKVC, CC);
    // 3) y = attention (2-term fp16 HMMA flash, base-2 softmax)
    attn_mma<<<dim3(TT/128, BB*HH), 256, ATT_SMEM>>>(qsh, qsl, ks, vs, y);
    // 4) x1 = y @ w_aproj + b_aproj + x
    hmma_gemm<2><<<dim3(CC/128, NROWS/128), 256, GEMM_SMEM>>>(
        y, wah, wal, b_aproj, x, x1, nullptr, nullptr, nullptr, nullptr, NROWS, CC, CC);
    // 5) h2 = ln2(x1)
    ln_h_kernel<<<NROWS/8, 256>>>(x1, ln2_g, ln2_b, h2);
    // 6) fc = gelu(h2 @ w_fc + b_fc)
    hmma_gemm<1><<<dim3(FFC/128, NROWS/128), 256, GEMM_SMEM>>>(
        h2, wfh, wfl, b_fc, nullptr, nullptr, fc, nullptr, nullptr, nullptr, NROWS, FFC, CC);
    // 7) out = fc @ w_mproj + b_mproj + x1
    hmma_gemm<2><<<dim3(CC/128, NROWS/128), 256, GEMM_SMEM>>>(
        fc, wmh, wml, b_mproj, x1, out, nullptr, nullptr, nullptr, nullptr, NROWS, CC, FFC);
}

// round 7
// speedup vs baseline: 4.1105x; 1.1066x over previous
#include <cuda_runtime.h>
#include <cuda_fp16.h>
#include <math.h>
#include <stdint.h>

// Problem constants
#define BB 4
#define TT 2048
#define CC 768
#define HH 12
#define DD 64
#define NROWS (BB*TT)          // 8192
#define QKVC (3*CC)            // 2304
#define FFC (4*CC)             // 3072

#define QSCALE (0.125f * 1.4426950408889634f)   // 1/sqrt(D) * log2(e)

// ================= scratch (allocation-free: __device__ globals) =================
__device__ __half g_h1[NROWS*CC];
__device__ __half g_y [NROWS*CC];
__device__ float  g_x1[NROWS*CC];
__device__ __half g_h2[NROWS*CC];
__device__ __half g_fc[NROWS*FFC];
__device__ __half g_wqh[QKVC*CC], g_wql[QKVC*CC];   // [N][K] K-major, hi+lo
__device__ __half g_wah[CC*CC],   g_wal[CC*CC];
__device__ __half g_wfh[FFC*CC],  g_wfl[FFC*CC];
__device__ __half g_wmh[CC*FFC],  g_wml[CC*FFC];
// per-head q/k/v: [b*H+h][T][64]; Q split hi/lo, K/V single
__device__ __half g_qsh[NROWS*CC], g_qsl[NROWS*CC];
__device__ __half g_ks [NROWS*CC];
__device__ __half g_vs [NROWS*CC];

__device__ __forceinline__ void split2h(float v, __half& h, __half& l) {
    h = __float2half_rn(v);
    l = __float2half_rn(v - __half2float(h));
}
__device__ __forceinline__ uint32_t packh2(__half a, __half b) {
    return (uint32_t)__half_as_ushort(a) | ((uint32_t)__half_as_ushort(b) << 16);
}
__device__ __forceinline__ uint32_t smem_u32(const void* p) {
    uint32_t a;
    asm("{ .reg .u64 t; cvta.to.shared.u64 t, %1; cvt.u32.u64 %0, t; }" : "=r"(a) : "l"(p));
    return a;
}
__device__ __forceinline__ void cp16(uint32_t saddr, const void* g) {
    asm volatile("cp.async.cg.shared.global [%0], [%1], 16;" :: "r"(saddr), "l"(g));
}
#define CP_COMMIT() asm volatile("cp.async.commit_group;" ::: "memory")
#define CP_WAIT1()  asm volatile("cp.async.wait_group 1;" ::: "memory")
#define CP_WAIT0()  asm volatile("cp.async.wait_group 0;" ::: "memory")

__device__ __forceinline__ void ldm_x4(uint32_t* r, uint32_t addr) {
    asm volatile("ldmatrix.sync.aligned.m8n8.x4.shared.b16 {%0,%1,%2,%3}, [%4];"
        : "=r"(r[0]), "=r"(r[1]), "=r"(r[2]), "=r"(r[3]) : "r"(addr));
}
__device__ __forceinline__ void ldm_x4_trans(uint32_t* r, uint32_t addr) {
    asm volatile("ldmatrix.sync.aligned.m8n8.x4.trans.shared.b16 {%0,%1,%2,%3}, [%4];"
        : "=r"(r[0]), "=r"(r[1]), "=r"(r[2]), "=r"(r[3]) : "r"(addr));
}
__device__ __forceinline__ void mma_f16(float* c, const uint32_t* a, const uint32_t* b) {
    asm volatile("mma.sync.aligned.m16n8k16.row.col.f32.f16.f16.f32 "
        "{%0,%1,%2,%3}, {%4,%5,%6,%7}, {%8,%9}, {%0,%1,%2,%3};"
        : "+f"(c[0]), "+f"(c[1]), "+f"(c[2]), "+f"(c[3])
        : "r"(a[0]), "r"(a[1]), "r"(a[2]), "r"(a[3]), "r"(b[0]), "r"(b[1]));
}
#define SMEM_SWIZZLE_128B(o) ((o) ^ (((o) >> 3) & 0x70))

__device__ __forceinline__ float gelu_tanh(float v) {
    const float c = 0.7978845608028654f;
    float u = c * (v + 0.044715f * v * v * v);
    return 0.5f * v * (1.0f + tanhf(u));
}

// ================= weight transpose + split: w[K,N] -> wt_hi/lo[N,K] fp16 =================
__global__ __launch_bounds__(256) void tsplit_kernel(const float* __restrict__ w,
                                                     __half* __restrict__ th,
                                                     __half* __restrict__ tl,
                                                     int K, int N)
{
    __shared__ float tile[32][33];
    const int tx = threadIdx.x & 31, ty = threadIdx.x >> 5;   // 32x8
    const int n0 = blockIdx.x * 32, k0 = blockIdx.y * 32;
    #pragma unroll
    for (int r = 0; r < 4; ++r)
        tile[ty + 8*r][tx] = w[(size_t)(k0 + ty + 8*r) * N + n0 + tx];
    __syncthreads();
    #pragma unroll
    for (int r = 0; r < 4; ++r) {
        const float v = tile[tx][ty + 8*r];
        __half h, l; split2h(v, h, l);
        const size_t o = (size_t)(n0 + ty + 8*r) * K + k0 + tx;
        th[o] = h; tl[o] = l;
    }
}

// ================= LayerNorm -> single fp16 =================
__global__ __launch_bounds__(256) void ln_h_kernel(const float* __restrict__ x,
                                                   const float* __restrict__ g,
                                                   const float* __restrict__ bt,
                                                   __half* __restrict__ oh)
{
    const int row  = blockIdx.x * 8 + (threadIdx.x >> 5);
    const int lane = threadIdx.x & 31;
    const float* xr = x + (size_t)row * CC;

    float4 v[6];
    float sum = 0.f;
    #pragma unroll
    for (int i = 0; i < 6; ++i) {
        v[i] = *(const float4*)(xr + lane*4 + i*128);
        sum += (v[i].x + v[i].y) + (v[i].z + v[i].w);
    }
    #pragma unroll
    for (int off = 16; off > 0; off >>= 1) sum += __shfl_xor_sync(0xffffffffu, sum, off);
    const float mu = sum * (1.0f/768.0f);
    float var = 0.f;
    #pragma unroll
    for (int i = 0; i < 6; ++i) {
        float dx;
        dx = v[i].x - mu; var += dx*dx;  dx = v[i].y - mu; var += dx*dx;
        dx = v[i].z - mu; var += dx*dx;  dx = v[i].w - mu; var += dx*dx;
    }
    #pragma unroll
    for (int off = 16; off > 0; off >>= 1) var += __shfl_xor_sync(0xffffffffu, var, off);
    const float rstd = rsqrtf(var * (1.0f/768.0f) + 1e-5f);

    #pragma unroll
    for (int i = 0; i < 6; ++i) {
        const int col = lane*4 + i*128;
        const float4 gg = *(const float4*)(g  + col);
        const float4 bb = *(const float4*)(bt + col);
        const float r0 = (v[i].x - mu)*rstd*gg.x + bb.x;
        const float r1 = (v[i].y - mu)*rstd*gg.y + bb.y;
        const float r2 = (v[i].z - mu)*rstd*gg.z + bb.z;
        const float r3 = (v[i].w - mu)*rstd*gg.w + bb.w;
        const size_t o = (size_t)row * CC + col;
        *(uint2*)(oh + o) = make_uint2(
            packh2(__float2half_rn(r0), __float2half_rn(r1)),
            packh2(__float2half_rn(r2), __float2half_rn(r3)));
    }
}

// ================= 2-term fp16 HMMA GEMM, 2-stage pipeline, 2 CTAs/SM =================
// D[M,N] = A16[M,K] @ (Wh+Wl)^T + bias, epilogues:
// EPI 1 = bias+gelu -> fp16; EPI 2 = bias+res -> fp32; EPI 3 = qkv per-head (Q split, K/V single)
#define TEN_BYTES 18432              // 128 rows * 72 elems * 2B
#define STAGE_BYTES (3*TEN_BYTES)    // A, Bh, Bl  = 55296
#define GEMM_SMEM (2*STAGE_BYTES)    // 110592 -> 2 CTAs/SM
#define ROWB 144

template<int EPI>
__global__ __launch_bounds__(256, 2) void hmma_gemm(
    const __half* __restrict__ Aa,
    const __half* __restrict__ Bh, const __half* __restrict__ Bl,
    const float* __restrict__ bias, const float* __restrict__ res,
    float* __restrict__ outF, __half* __restrict__ outH, __half* __restrict__ outL,
    __half* __restrict__ oks, __half* __restrict__ ovs,
    int M, int N, int K)
{
    extern __shared__ __align__(1024) char smem[];
    const uint32_t sb = smem_u32(smem);

    const int t    = threadIdx.x;
    const int lane = t & 31;
    const int wid  = t >> 5;
    const int warp_m = wid >> 2;
    const int warp_n = wid & 3;
    const int n0 = blockIdx.x * 128;
    const int m0 = blockIdx.y * 128;

    float acc[4][4][4];
    #pragma unroll
    for (int i = 0; i < 4; ++i)
        #pragma unroll
        for (int j = 0; j < 4; ++j)
            #pragma unroll
            for (int e = 0; e < 4; ++e) acc[i][j][e] = 0.f;

    // A ldmatrix addressing (x4, m16 x k16)
    const uint32_t aBase  = sb + 0*TEN_BYTES + (uint32_t)(warp_m*64 + (lane & 15)) * ROWB + (lane >> 4) * 16;
    // B ldmatrix addressing (x4, fn-pair: 16 rows x k16)
    //  g0(l0-7): rows r, kb+0 | g1: rows r, kb+16 | g2: rows r+8, kb+0 | g3: rows r+8, kb+16
    const uint32_t bRow   = (uint32_t)((lane & 7) + ((lane >> 4) << 3));
    const uint32_t bCol16 = (uint32_t)(((lane >> 3) & 1) * 16);
    const uint32_t bBaseH = sb + 1*TEN_BYTES + (uint32_t)(warp_n*32 + bRow) * ROWB + bCol16;
    const uint32_t bBaseL = bBaseH + TEN_BYTES;

    const int nch = K >> 6;

    auto load_stage = [&](int buf, int k0) {
        const uint32_t dst = sb + buf * STAGE_BYTES;
        #pragma unroll
        for (int i = 0; i < 4; ++i) {
            const int idx = i * 256 + t;
            const int row = idx >> 3;
            const int seg = idx & 7;
            const uint32_t so = (uint32_t)row * ROWB + seg * 16;
            const size_t ga = (size_t)(m0 + row) * K + k0 + seg * 8;
            const size_t gb = (size_t)(n0 + row) * K + k0 + seg * 8;
            cp16(dst + 0*TEN_BYTES + so, Aa + ga);
            cp16(dst + 1*TEN_BYTES + so, Bh + gb);
            cp16(dst + 2*TEN_BYTES + so, Bl + gb);
        }
    };

    load_stage(0, 0);
    CP_COMMIT();

    int buf = 0;
    for (int ch = 0; ch < nch; ++ch) {
        if (ch + 1 < nch) {
            load_stage(buf ^ 1, (ch + 1) << 6);
            CP_COMMIT();
            CP_WAIT1();
        } else {
            CP_WAIT0();
        }
        __syncthreads();

        const uint32_t st = (uint32_t)buf * STAGE_BYTES;
        #pragma unroll
        for (int ks = 0; ks < 4; ++ks) {
            const uint32_t kb = ks * 32;
            uint32_t af[4][4];
            #pragma unroll
            for (int fm = 0; fm < 4; ++fm)
                ldm_x4(af[fm], aBase + st + fm * (16 * ROWB) + kb);
            uint32_t bhf[2][4], blf[2][4];   // [pair][regs]: r0,r1 = fn=2p; r2,r3 = fn=2p+1
            #pragma unroll
            for (int p = 0; p < 2; ++p) {
                ldm_x4(bhf[p], bBaseH + st + p * (16 * ROWB) + kb);
                ldm_x4(blf[p], bBaseL + st + p * (16 * ROWB) + kb);
            }
            #pragma unroll
            for (int fm = 0; fm < 4; ++fm)
                #pragma unroll
                for (int fn = 0; fn < 4; ++fn) {
                    mma_f16(acc[fm][fn], af[fm], bhf[fn >> 1] + (fn & 1) * 2);
                    mma_f16(acc[fm][fn], af[fm], blf[fn >> 1] + (fn & 1) * 2);
                }
        }
        __syncthreads();
        buf ^= 1;
    }

    #pragma unroll
    for (int fm = 0; fm < 4; ++fm) {
        const int row0 = m0 + warp_m*64 + fm*16 + (lane >> 2);
        #pragma unroll
        for (int fn = 0; fn < 4; ++fn) {
            const int col = n0 + warp_n*32 + fn*8 + (lane & 3)*2;
            const float b0 = bias[col], b1 = bias[col + 1];
            float v0 = acc[fm][fn][0] + b0;
            float v1 = acc[fm][fn][1] + b1;
            float v2 = acc[fm][fn][2] + b0;
            float v3 = acc[fm][fn][3] + b1;
            if (EPI == 2) {
                const float2 r0 = *(const float2*)(res + (size_t)row0 * N + col);
                const float2 r1 = *(const float2*)(res + (size_t)(row0 + 8) * N + col);
                v0 += r0.x; v1 += r0.y; v2 += r1.x; v3 += r1.y;
                *(float2*)(outF + (size_t)row0 * N + col)       = make_float2(v0, v1);
                *(float2*)(outF + (size_t)(row0 + 8) * N + col) = make_float2(v2, v3);
            }
            if (EPI == 1) {
                v0 = gelu_tanh(v0); v1 = gelu_tanh(v1);
                v2 = gelu_tanh(v2); v3 = gelu_tanh(v3);
                *(uint32_t*)(outH + (size_t)row0 * N + col) =
                    packh2(__float2half_rn(v0), __float2half_rn(v1));
                *(uint32_t*)(outH + (size_t)(row0 + 8) * N + col) =
                    packh2(__float2half_rn(v2), __float2half_rn(v3));
            }
            if (EPI == 3) {
                const int which = col / CC;
                const int cc = col - which * CC;
                const int hh = cc >> 6, d = cc & 63;
                const int b0r = row0 >> 11, t0r = row0 & 2047;
                const int b1r = (row0 + 8) >> 11, t1r = (row0 + 8) & 2047;
                const size_t base0 = ((size_t)(b0r * HH + hh) * TT + t0r) * 64 + d;
                const size_t base1 = ((size_t)(b1r * HH + hh) * TT + t1r) * 64 + d;
                if (which == 0) {
                    v0 *= QSCALE; v1 *= QSCALE; v2 *= QSCALE; v3 *= QSCALE;
                    __half h0,l0,h1,l1;
                    split2h(v0,h0,l0); split2h(v1,h1,l1);
                    *(uint32_t*)(outH + base0) = packh2(h0,h1);
                    *(uint32_t*)(outL + base0) = packh2(l0,l1);
                    split2h(v2,h0,l0); split2h(v3,h1,l1);
                    *(uint32_t*)(outH + base1) = packh2(h0,h1);
                    *(uint32_t*)(outL + base1) = packh2(l0,l1);
                } else {
                    __half* o = (which == 1) ? oks : ovs;
                    *(uint32_t*)(o + base0) = packh2(__float2half_rn(v0), __float2half_rn(v1));
                    *(uint32_t*)(o + base1) = packh2(__float2half_rn(v2), __float2half_rn(v3));
                }
            }
        }
    }
}

// ================= 2-term fp16 HMMA flash attention, 3-stage KV pipeline =================
// Q-tile 128 rows (8 warps x m16), K-tile 64, per-head layout [bh][T][64].
// smem: Qh 16K | Ql 16K | 3 KV stages of (K 8K | V 8K)
#define ATT_SMEM 81920
__global__ __launch_bounds__(256, 1) void attn_mma(
    const __half* __restrict__ qh, const __half* __restrict__ ql,
    const __half* __restrict__ kk, const __half* __restrict__ vv,
    __half* __restrict__ yy)
{
    extern __shared__ __align__(1024) char smem[];
    const uint32_t sb = smem_u32(smem);
    enum { QH_O = 0, QL_O = 16384, KV0 = 32768, KV_STRIDE = 16384,
           K_O = 0, V_O = 8192 };

    const int t = threadIdx.x, lane = t & 31, wid = t >> 5;
    const int qt = (int)(gridDim.x - 1) - (int)blockIdx.x;   // big tiles first
    const int bh = blockIdx.y;
    const int qbase = qt * 128;
    const size_t hb = (size_t)bh * TT * 64;
    const int warpQ = wid * 16;

    // Q copy
    #pragma unroll
    for (int i = 0; i < 4; ++i) {
        const int idx = t + i * 256;
        const int row = idx >> 3, seg = idx & 7;
        const uint32_t so = SMEM_SWIZZLE_128B((uint32_t)(row * 128 + seg * 16));
        const size_t g = hb + (size_t)(qbase + row) * 64 + seg * 8;
        cp16(sb + QH_O + so, qh + g);
        cp16(sb + QL_O + so, ql + g);
    }
    auto load_kv = [&](int buf, int kt) {
        const uint32_t dst = sb + KV0 + buf * KV_STRIDE;
        #pragma unroll
        for (int i = 0; i < 2; ++i) {
            const int idx = t + i * 256;
            const int row = idx >> 3, seg = idx & 7;
            const uint32_t so = SMEM_SWIZZLE_128B((uint32_t)(row * 128 + seg * 16));
            const size_t g = hb + (size_t)(kt * 64 + row) * 64 + seg * 8;
            cp16(dst + K_O + so, kk + g);
            cp16(dst + V_O + so, vv + g);
        }
    };
    const int nkt = 2 * qt + 2;
    load_kv(0, 0);
    CP_COMMIT();
    load_kv(1, 1);
    CP_COMMIT();

    uint32_t qah[4][4], qal[4][4];
    float o[8][4];
    #pragma unroll
    for (int j = 0; j < 8; ++j)
        #pragma unroll
        for (int e = 0; e < 4; ++e) o[j][e] = 0.f;
    float m0r = -1e30f, m1r = -1e30f, l0r = 0.f, l1r = 0.f;

    int buf = 0;
    for (int kt = 0; kt < nkt; ++kt) {
        if (kt == nkt - 1) { CP_WAIT0(); } else { CP_WAIT1(); }
        __syncthreads();
        if (kt + 2 < nkt) {
            int nb = buf + 2; if (nb >= 3) nb -= 3;
            load_kv(nb, kt + 2);
            CP_COMMIT();
        }

        if (kt == 0) {
            const uint32_t qrow = (uint32_t)(warpQ + (lane & 15));
            const uint32_t qbyt = (uint32_t)((lane >> 4) * 16);
            #pragma unroll
            for (int s = 0; s < 4; ++s) {
                const uint32_t so = SMEM_SWIZZLE_128B(qrow * 128 + s * 32 + qbyt);
                ldm_x4(qah[s], sb + QH_O + so);
                ldm_x4(qal[s], sb + QL_O + so);
            }
        }
        const uint32_t st = sb + KV0 + buf * KV_STRIDE;

        // ---- S = (Qh+Ql) K16^T ----
        float sacc[8][4];
        #pragma unroll
        for (int j = 0; j < 8; ++j) { sacc[j][0]=0.f; sacc[j][1]=0.f; sacc[j][2]=0.f; sacc[j][3]=0.f; }
        #pragma unroll
        for (int j = 0; j < 8; ++j) {
            const uint32_t krow = (uint32_t)(j * 8 + (lane & 7));
            const uint32_t kbyt = (uint32_t)(((lane >> 3) & 3) * 16);
            const uint32_t so0 = SMEM_SWIZZLE_128B(krow * 128 + kbyt);
            const uint32_t so1 = SMEM_SWIZZLE_128B(krow * 128 + 64 + kbyt);
            uint32_t kb0[4], kb1[4];
            ldm_x4(kb0, st + K_O + so0);
            ldm_x4(kb1, st + K_O + so1);
            mma_f16(sacc[j], qah[0], kb0 + 0); mma_f16(sacc[j], qah[1], kb0 + 2);
            mma_f16(sacc[j], qah[2], kb1 + 0); mma_f16(sacc[j], qah[3], kb1 + 2);
            mma_f16(sacc[j], qal[0], kb0 + 0); mma_f16(sacc[j], qal[1], kb0 + 2);
            mma_f16(sacc[j], qal[2], kb1 + 0); mma_f16(sacc[j], qal[3], kb1 + 2);
        }

        // ---- causal mask (last two K-tiles only) ----
        if (kt >= 2 * qt) {
            const int r0 = qbase + warpQ + (lane >> 2);
            #pragma unroll
            for (int j = 0; j < 8; ++j) {
                const int c = kt * 64 + j * 8 + (lane & 3) * 2;
                if (c     > r0)     sacc[j][0] = -1e30f;
                if (c + 1 > r0)     sacc[j][1] = -1e30f;
                if (c     > r0 + 8) sacc[j][2] = -1e30f;
                if (c + 1 > r0 + 8) sacc[j][3] = -1e30f;
            }
        }

        // ---- online softmax (base-2) ----
        float tm0 = -1e30f, tm1 = -1e30f;
        #pragma unroll
        for (int j = 0; j < 8; ++j) {
            tm0 = fmaxf(tm0, fmaxf(sacc[j][0], sacc[j][1]));
            tm1 = fmaxf(tm1, fmaxf(sacc[j][2], sacc[j][3]));
        }
        tm0 = fmaxf(tm0, __shfl_xor_sync(0xffffffffu, tm0, 1));
        tm0 = fmaxf(tm0, __shfl_xor_sync(0xffffffffu, tm0, 2));
        tm1 = fmaxf(tm1, __shfl_xor_sync(0xffffffffu, tm1, 1));
        tm1 = fmaxf(tm1, __shfl_xor_sync(0xffffffffu, tm1, 2));
        const float mn0 = fmaxf(m0r, tm0), mn1 = fmaxf(m1r, tm1);
        const float al0 = exp2f(m0r - mn0), al1 = exp2f(m1r - mn1);
        m0r = mn0; m1r = mn1;
        float rs0 = 0.f, rs1 = 0.f;
        #pragma unroll
        for (int j = 0; j < 8; ++j) {
            sacc[j][0] = exp2f(sacc[j][0] - mn0);
            sacc[j][1] = exp2f(sacc[j][1] - mn0);
            sacc[j][2] = exp2f(sacc[j][2] - mn1);
            sacc[j][3] = exp2f(sacc[j][3] - mn1);
            rs0 += sacc[j][0] + sacc[j][1];
            rs1 += sacc[j][2] + sacc[j][3];
        }
        rs0 += __shfl_xor_sync(0xffffffffu, rs0, 1);
        rs0 += __shfl_xor_sync(0xffffffffu, rs0, 2);
        rs1 += __shfl_xor_sync(0xffffffffu, rs1, 1);
        rs1 += __shfl_xor_sync(0xffffffffu, rs1, 2);
        l0r = l0r * al0 + rs0;
        l1r = l1r * al1 + rs1;
        #pragma unroll
        for (int j = 0; j < 8; ++j) {
            o[j][0] *= al0; o[j][1] *= al0; o[j][2] *= al1; o[j][3] *= al1;
        }

        // ---- P -> split fp16 A-operand fragments (from exact fp32 regs) ----
        uint32_t pah[4][4], pal[4][4];
        #pragma unroll
        for (int s = 0; s < 4; ++s) {
            __half h0, l0, h1, l1;
            split2h(sacc[2*s][0], h0, l0);   split2h(sacc[2*s][1], h1, l1);
            pah[s][0] = packh2(h0, h1);      pal[s][0] = packh2(l0, l1);
            split2h(sacc[2*s][2], h0, l0);   split2h(sacc[2*s][3], h1, l1);
            pah[s][1] = packh2(h0, h1);      pal[s][1] = packh2(l0, l1);
            split2h(sacc[2*s+1][0], h0, l0); split2h(sacc[2*s+1][1], h1, l1);
            pah[s][2] = packh2(h0, h1);      pal[s][2] = packh2(l0, l1);
            split2h(sacc[2*s+1][2], h0, l0); split2h(sacc[2*s+1][3], h1, l1);
            pah[s][3] = packh2(h0, h1);      pal[s][3] = packh2(l0, l1);
        }

        // ---- O += (Ph+Pl) V16 (V^T via ldmatrix.trans) ----
        #pragma unroll
        for (int jp = 0; jp < 4; ++jp) {
            #pragma unroll
            for (int s = 0; s < 4; ++s) {
                const uint32_t vrow = (uint32_t)(s * 16 + (lane & 15));
                const uint32_t vbyt = (uint32_t)(jp * 32 + (lane >> 4) * 16);
                const uint32_t so = SMEM_SWIZZLE_128B(vrow * 128 + vbyt);
                uint32_t vb[4];
                ldm_x4_trans(vb, st + V_O + so);
                mma_f16(o[2*jp],     pah[s], vb + 0);
                mma_f16(o[2*jp + 1], pah[s], vb + 2);
                mma_f16(o[2*jp],     pal[s], vb + 0);
                mma_f16(o[2*jp + 1], pal[s], vb + 2);
            }
        }
        ++buf; if (buf >= 3) buf -= 3;
    }

    // ---- epilogue: normalize, write y (single fp16) ----
    const float inv0 = 1.0f / l0r, inv1 = 1.0f / l1r;
    const int b = bh / HH, h = bh - b * HH;
    const size_t row0 = (size_t)b * TT + qbase + warpQ + (lane >> 2);
    #pragma unroll
    for (int j = 0; j < 8; ++j) {
        const int col = h * 64 + j * 8 + (lane & 3) * 2;
        *(uint32_t*)(yy + row0 * CC + col) =
            packh2(__float2half_rn(o[j][0] * inv0), __float2half_rn(o[j][1] * inv0));
        *(uint32_t*)(yy + (row0 + 8) * CC + col) =
            packh2(__float2half_rn(o[j][2] * inv1), __float2half_rn(o[j][3] * inv1));
    }
}

// ================= launch =================
extern "C" void kernel_launch(void* const* d_in, const int* in_sizes, int n_in,
                              void* d_out, int out_size)
{
    const float* x       = (const float*)d_in[0];
    const float* ln1_g   = (const float*)d_in[1];
    const float* ln1_b   = (const float*)d_in[2];
    const float* w_attn  = (const float*)d_in[3];
    const float* b_attn  = (const float*)d_in[4];
    const float* w_aproj = (const float*)d_in[5];
    const float* b_aproj = (const float*)d_in[6];
    const float* ln2_g   = (const float*)d_in[7];
    const float* ln2_b   = (const float*)d_in[8];
    const float* w_fc    = (const float*)d_in[9];
    const float* b_fc    = (const float*)d_in[10];
    const float* w_mproj = (const float*)d_in[11];
    const float* b_mproj = (const float*)d_in[12];
    float* out = (float*)d_out;

    __half *h1,*y,*h2,*fc;
    __half *wqh,*wql,*wah,*wal,*wfh,*wfl,*wmh,*wml;
    __half *qsh,*qsl,*ks,*vs;
    float *x1;
    cudaGetSymbolAddress((void**)&h1,  g_h1);
    cudaGetSymbolAddress((void**)&y,   g_y);
    cudaGetSymbolAddress((void**)&x1,  g_x1);
    cudaGetSymbolAddress((void**)&h2,  g_h2);
    cudaGetSymbolAddress((void**)&fc,  g_fc);
    cudaGetSymbolAddress((void**)&wqh, g_wqh); cudaGetSymbolAddress((void**)&wql, g_wql);
    cudaGetSymbolAddress((void**)&wah, g_wah); cudaGetSymbolAddress((void**)&wal, g_wal);
    cudaGetSymbolAddress((void**)&wfh, g_wfh); cudaGetSymbolAddress((void**)&wfl, g_wfl);
    cudaGetSymbolAddress((void**)&wmh, g_wmh); cudaGetSymbolAddress((void**)&wml, g_wml);
    cudaGetSymbolAddress((void**)&qsh, g_qsh); cudaGetSymbolAddress((void**)&qsl, g_qsl);
    cudaGetSymbolAddress((void**)&ks,  g_ks);  cudaGetSymbolAddress((void**)&vs,  g_vs);

    cudaFuncSetAttribute(hmma_gemm<1>, cudaFuncAttributeMaxDynamicSharedMemorySize, GEMM_SMEM);
    cudaFuncSetAttribute(hmma_gemm<2>, cudaFuncAttributeMaxDynamicSharedMemorySize, GEMM_SMEM);
    cudaFuncSetAttribute(hmma_gemm<3>, cudaFuncAttributeMaxDynamicSharedMemorySize, GEMM_SMEM);
    cudaFuncSetAttribute(attn_mma,     cudaFuncAttributeMaxDynamicSharedMemorySize, ATT_SMEM);

    // weight transpose + split
    tsplit_kernel<<<dim3(QKVC/32, CC/32),  dim3(256)>>>(w_attn,  wqh, wql, CC,  QKVC);
    tsplit_kernel<<<dim3(CC/32,   CC/32),  dim3(256)>>>(w_aproj, wah, wal, CC,  CC);
    tsplit_kernel<<<dim3(FFC/32,  CC/32),  dim3(256)>>>(w_fc,    wfh, wfl, CC,  FFC);
    tsplit_kernel<<<dim3(CC/32,   FFC/32), dim3(256)>>>(w_mproj, wmh, wml, FFC, CC);

    // 1) h1 = ln1(x)  (single fp16)
    ln_h_kernel<<<NROWS/8, 256>>>(x, ln1_g, ln1_b, h1);
    // 2) q/k/v = per-head(h1 @ w_attn + b_attn); Q split+scaled, K/V single
    hmma_gemm<3><<<dim3(QKVC/128, NROWS/128), 256, GEMM_SMEM>>>(
        h1, wqh, wql, b_attn, nullptr, nullptr, qsh, qsl, ks, vs, NROWS, QKVC, CC);
    // 3) y = attention (2-term fp16 HMMA flash, base-2 softmax)
    attn_mma<<<dim3(TT/128, BB*HH), 256, ATT_SMEM>>>(qsh, qsl, ks, vs, y);
    // 4) x1 = y @ w_aproj + b_aproj + x
    hmma_gemm<2><<<dim3(CC/128, NROWS/128), 256, GEMM_SMEM>>>(
        y, wah, wal, b_aproj, x, x1, nullptr, nullptr, nullptr, nullptr, NROWS, CC, CC);
    // 5) h2 = ln2(x1)
    ln_h_kernel<<<NROWS/8, 256>>>(x1, ln2_g, ln2_b, h2);
    // 6) fc = gelu(h2 @ w_fc + b_fc)
    hmma_gemm<1><<<dim3(FFC/128, NROWS/128), 256, GEMM_SMEM>>>(
        h2, wfh, wfl, b_fc, nullptr, nullptr, fc, nullptr, nullptr, nullptr, NROWS, FFC, CC);
    // 7) out = fc @ w_mproj + b_mproj + x1
    hmma_gemm<2><<<dim3(CC/128, NROWS/128), 256, GEMM_SMEM>>>(
        fc, wmh, wml, b_mproj, x1, out, nullptr, nullptr, nullptr, nullptr, NROWS, CC, FFC);
}

// round 8
// speedup vs baseline: 6.6513x; 1.6181x over previous
#include <cuda_runtime.h>
#include <cuda_fp16.h>
#include <math.h>
#include <stdint.h>

// Problem constants
#define BB 4
#define TT 2048
#define CC 768
#define HH 12
#define DD 64
#define NROWS (BB*TT)          // 8192
#define QKVC (3*CC)            // 2304
#define FFC (4*CC)             // 3072

#define QSCALE (0.125f * 1.4426950408889634f)   // 1/sqrt(D) * log2(e)

// ================= scratch (allocation-free: __device__ globals) =================
__device__ __half g_h1[NROWS*CC];
__device__ __half g_y [NROWS*CC];
__device__ float  g_x1[NROWS*CC];
__device__ __half g_h2[NROWS*CC];
__device__ __half g_fc[NROWS*FFC];
__device__ __half g_wq[QKVC*CC];   // [N][K] K-major, single fp16
__device__ __half g_wa[CC*CC];
__device__ __half g_wf[FFC*CC];
__device__ __half g_wm[CC*FFC];
// per-head q/k/v: [b*H+h][T][64], single fp16 (Q pre-scaled)
__device__ __half g_qs[NROWS*CC];
__device__ __half g_ks[NROWS*CC];
__device__ __half g_vs[NROWS*CC];

__device__ __forceinline__ uint32_t packh2(__half a, __half b) {
    return (uint32_t)__half_as_ushort(a) | ((uint32_t)__half_as_ushort(b) << 16);
}
__device__ __forceinline__ uint32_t smem_u32(const void* p) {
    uint32_t a;
    asm("{ .reg .u64 t; cvta.to.shared.u64 t, %1; cvt.u32.u64 %0, t; }" : "=r"(a) : "l"(p));
    return a;
}
__device__ __forceinline__ void cp16(uint32_t saddr, const void* g) {
    asm volatile("cp.async.cg.shared.global [%0], [%1], 16;" :: "r"(saddr), "l"(g));
}
#define CP_COMMIT() asm volatile("cp.async.commit_group;" ::: "memory")
#define CP_WAIT1()  asm volatile("cp.async.wait_group 1;" ::: "memory")
#define CP_WAIT0()  asm volatile("cp.async.wait_group 0;" ::: "memory")

__device__ __forceinline__ void ldm_x4(uint32_t* r, uint32_t addr) {
    asm volatile("ldmatrix.sync.aligned.m8n8.x4.shared.b16 {%0,%1,%2,%3}, [%4];"
        : "=r"(r[0]), "=r"(r[1]), "=r"(r[2]), "=r"(r[3]) : "r"(addr));
}
__device__ __forceinline__ void ldm_x4_trans(uint32_t* r, uint32_t addr) {
    asm volatile("ldmatrix.sync.aligned.m8n8.x4.trans.shared.b16 {%0,%1,%2,%3}, [%4];"
        : "=r"(r[0]), "=r"(r[1]), "=r"(r[2]), "=r"(r[3]) : "r"(addr));
}
__device__ __forceinline__ void mma_f16(float* c, const uint32_t* a, const uint32_t* b) {
    asm volatile("mma.sync.aligned.m16n8k16.row.col.f32.f16.f16.f32 "
        "{%0,%1,%2,%3}, {%4,%5,%6,%7}, {%8,%9}, {%0,%1,%2,%3};"
        : "+f"(c[0]), "+f"(c[1]), "+f"(c[2]), "+f"(c[3])
        : "r"(a[0]), "r"(a[1]), "r"(a[2]), "r"(a[3]), "r"(b[0]), "r"(b[1]));
}
#define SMEM_SWIZZLE_128B(o) ((o) ^ (((o) >> 3) & 0x70))

__device__ __forceinline__ float gelu_tanh(float v) {
    const float c = 0.7978845608028654f;
    float u = c * (v + 0.044715f * v * v * v);
    return 0.5f * v * (1.0f + tanhf(u));
}

// ================= weight transpose: w[K,N] -> wt[N,K] fp16 =================
__global__ __launch_bounds__(256) void tsplit_kernel(const float* __restrict__ w,
                                                     __half* __restrict__ th,
                                                     int K, int N)
{
    __shared__ float tile[32][33];
    const int tx = threadIdx.x & 31, ty = threadIdx.x >> 5;   // 32x8
    const int n0 = blockIdx.x * 32, k0 = blockIdx.y * 32;
    #pragma unroll
    for (int r = 0; r < 4; ++r)
        tile[ty + 8*r][tx] = w[(size_t)(k0 + ty + 8*r) * N + n0 + tx];
    __syncthreads();
    #pragma unroll
    for (int r = 0; r < 4; ++r) {
        th[(size_t)(n0 + ty + 8*r) * K + k0 + tx] = __float2half_rn(tile[tx][ty + 8*r]);
    }
}

// ================= LayerNorm -> single fp16 =================
__global__ __launch_bounds__(256) void ln_h_kernel(const float* __restrict__ x,
                                                   const float* __restrict__ g,
                                                   const float* __restrict__ bt,
                                                   __half* __restrict__ oh)
{
    const int row  = blockIdx.x * 8 + (threadIdx.x >> 5);
    const int lane = threadIdx.x & 31;
    const float* xr = x + (size_t)row * CC;

    float4 v[6];
    float sum = 0.f;
    #pragma unroll
    for (int i = 0; i < 6; ++i) {
        v[i] = *(const float4*)(xr + lane*4 + i*128);
        sum += (v[i].x + v[i].y) + (v[i].z + v[i].w);
    }
    #pragma unroll
    for (int off = 16; off > 0; off >>= 1) sum += __shfl_xor_sync(0xffffffffu, sum, off);
    const float mu = sum * (1.0f/768.0f);
    float var = 0.f;
    #pragma unroll
    for (int i = 0; i < 6; ++i) {
        float dx;
        dx = v[i].x - mu; var += dx*dx;  dx = v[i].y - mu; var += dx*dx;
        dx = v[i].z - mu; var += dx*dx;  dx = v[i].w - mu; var += dx*dx;
    }
    #pragma unroll
    for (int off = 16; off > 0; off >>= 1) var += __shfl_xor_sync(0xffffffffu, var, off);
    const float rstd = rsqrtf(var * (1.0f/768.0f) + 1e-5f);

    #pragma unroll
    for (int i = 0; i < 6; ++i) {
        const int col = lane*4 + i*128;
        const float4 gg = *(const float4*)(g  + col);
        const float4 bb = *(const float4*)(bt + col);
        const float r0 = (v[i].x - mu)*rstd*gg.x + bb.x;
        const float r1 = (v[i].y - mu)*rstd*gg.y + bb.y;
        const float r2 = (v[i].z - mu)*rstd*gg.z + bb.z;
        const float r3 = (v[i].w - mu)*rstd*gg.w + bb.w;
        const size_t o = (size_t)row * CC + col;
        *(uint2*)(oh + o) = make_uint2(
            packh2(__float2half_rn(r0), __float2half_rn(r1)),
            packh2(__float2half_rn(r2), __float2half_rn(r3)));
    }
}

// ================= single-term fp16 HMMA GEMM, 2-stage pipeline, 2 CTAs/SM =================
// D[M,N] = A16[M,K] @ W16^T + bias, epilogues:
// EPI 1 = bias+gelu -> fp16; EPI 2 = bias+res -> fp32; EPI 3 = qkv per-head
#define TEN_BYTES 18432              // 128 rows * 72 elems * 2B
#define STAGE_BYTES (2*TEN_BYTES)    // A, B = 36864
#define GEMM_SMEM (2*STAGE_BYTES)    // 73728 -> 2 CTAs/SM easily
#define ROWB 144

template<int EPI>
__global__ __launch_bounds__(256, 2) void hmma_gemm(
    const __half* __restrict__ Aa,
    const __half* __restrict__ Bw,
    const float* __restrict__ bias, const float* __restrict__ res,
    float* __restrict__ outF, __half* __restrict__ outH,
    __half* __restrict__ oks, __half* __restrict__ ovs,
    int M, int N, int K)
{
    extern __shared__ __align__(1024) char smem[];
    const uint32_t sb = smem_u32(smem);

    const int t    = threadIdx.x;
    const int lane = t & 31;
    const int wid  = t >> 5;
    const int warp_m = wid >> 2;
    const int warp_n = wid & 3;
    const int n0 = blockIdx.x * 128;
    const int m0 = blockIdx.y * 128;

    float acc[4][4][4];
    #pragma unroll
    for (int i = 0; i < 4; ++i)
        #pragma unroll
        for (int j = 0; j < 4; ++j)
            #pragma unroll
            for (int e = 0; e < 4; ++e) acc[i][j][e] = 0.f;

    // A ldmatrix addressing (x4, m16 x k16)
    const uint32_t aBase = sb + 0*TEN_BYTES + (uint32_t)(warp_m*64 + (lane & 15)) * ROWB + (lane >> 4) * 16;
    // B ldmatrix addressing (x4, fn-pair: 16 rows x k16)
    const uint32_t bRow   = (uint32_t)((lane & 7) + ((lane >> 4) << 3));
    const uint32_t bCol16 = (uint32_t)(((lane >> 3) & 1) * 16);
    const uint32_t bBase = sb + 1*TEN_BYTES + (uint32_t)(warp_n*32 + bRow) * ROWB + bCol16;

    const int nch = K >> 6;

    auto load_stage = [&](int buf, int k0) {
        const uint32_t dst = sb + buf * STAGE_BYTES;
        #pragma unroll
        for (int i = 0; i < 4; ++i) {
            const int idx = i * 256 + t;
            const int row = idx >> 3;
            const int seg = idx & 7;
            const uint32_t so = (uint32_t)row * ROWB + seg * 16;
            const size_t ga = (size_t)(m0 + row) * K + k0 + seg * 8;
            const size_t gb = (size_t)(n0 + row) * K + k0 + seg * 8;
            cp16(dst + 0*TEN_BYTES + so, Aa + ga);
            cp16(dst + 1*TEN_BYTES + so, Bw + gb);
        }
    };

    load_stage(0, 0);
    CP_COMMIT();

    int buf = 0;
    for (int ch = 0; ch < nch; ++ch) {
        if (ch + 1 < nch) {
            load_stage(buf ^ 1, (ch + 1) << 6);
            CP_COMMIT();
            CP_WAIT1();
        } else {
            CP_WAIT0();
        }
        __syncthreads();

        const uint32_t st = (uint32_t)buf * STAGE_BYTES;
        #pragma unroll
        for (int ks = 0; ks < 4; ++ks) {
            const uint32_t kb = ks * 32;
            uint32_t af[4][4];
            #pragma unroll
            for (int fm = 0; fm < 4; ++fm)
                ldm_x4(af[fm], aBase + st + fm * (16 * ROWB) + kb);
            uint32_t bf[2][4];   // [pair][regs]: r0,r1 = fn=2p; r2,r3 = fn=2p+1
            #pragma unroll
            for (int p = 0; p < 2; ++p)
                ldm_x4(bf[p], bBase + st + p * (16 * ROWB) + kb);
            #pragma unroll
            for (int fm = 0; fm < 4; ++fm)
                #pragma unroll
                for (int fn = 0; fn < 4; ++fn)
                    mma_f16(acc[fm][fn], af[fm], bf[fn >> 1] + (fn & 1) * 2);
        }
        __syncthreads();
        buf ^= 1;
    }

    #pragma unroll
    for (int fm = 0; fm < 4; ++fm) {
        const int row0 = m0 + warp_m*64 + fm*16 + (lane >> 2);
        #pragma unroll
        for (int fn = 0; fn < 4; ++fn) {
            const int col = n0 + warp_n*32 + fn*8 + (lane & 3)*2;
            const float b0 = bias[col], b1 = bias[col + 1];
            float v0 = acc[fm][fn][0] + b0;
            float v1 = acc[fm][fn][1] + b1;
            float v2 = acc[fm][fn][2] + b0;
            float v3 = acc[fm][fn][3] + b1;
            if (EPI == 2) {
                const float2 r0 = *(const float2*)(res + (size_t)row0 * N + col);
                const float2 r1 = *(const float2*)(res + (size_t)(row0 + 8) * N + col);
                v0 += r0.x; v1 += r0.y; v2 += r1.x; v3 += r1.y;
                *(float2*)(outF + (size_t)row0 * N + col)       = make_float2(v0, v1);
                *(float2*)(outF + (size_t)(row0 + 8) * N + col) = make_float2(v2, v3);
            }
            if (EPI == 1) {
                v0 = gelu_tanh(v0); v1 = gelu_tanh(v1);
                v2 = gelu_tanh(v2); v3 = gelu_tanh(v3);
                *(uint32_t*)(outH + (size_t)row0 * N + col) =
                    packh2(__float2half_rn(v0), __float2half_rn(v1));
                *(uint32_t*)(outH + (size_t)(row0 + 8) * N + col) =
                    packh2(__float2half_rn(v2), __float2half_rn(v3));
            }
            if (EPI == 3) {
                const int which = col / CC;
                const int cc = col - which * CC;
                const int hh = cc >> 6, d = cc & 63;
                const int b0r = row0 >> 11, t0r = row0 & 2047;
                const int b1r = (row0 + 8) >> 11, t1r = (row0 + 8) & 2047;
                const size_t base0 = ((size_t)(b0r * HH + hh) * TT + t0r) * 64 + d;
                const size_t base1 = ((size_t)(b1r * HH + hh) * TT + t1r) * 64 + d;
                const float sc = (which == 0) ? QSCALE : 1.0f;
                __half* o = (which == 0) ? outH : (which == 1) ? oks : ovs;
                *(uint32_t*)(o + base0) = packh2(__float2half_rn(v0 * sc), __float2half_rn(v1 * sc));
                *(uint32_t*)(o + base1) = packh2(__float2half_rn(v2 * sc), __float2half_rn(v3 * sc));
            }
        }
    }
}

// ================= single-term fp16 HMMA flash attention, 3-stage KV pipeline =============
// Q-tile 128 rows (8 warps x m16), K-tile 64, per-head layout [bh][T][64].
// smem: Q 16K | 3 KV stages of (K 8K | V 8K)
#define ATT_SMEM 65536
__global__ __launch_bounds__(256, 1) void attn_mma(
    const __half* __restrict__ qq,
    const __half* __restrict__ kk, const __half* __restrict__ vv,
    __half* __restrict__ yy)
{
    extern __shared__ __align__(1024) char smem[];
    const uint32_t sb = smem_u32(smem);
    enum { Q_O = 0, KV0 = 16384, KV_STRIDE = 16384, K_O = 0, V_O = 8192 };

    const int t = threadIdx.x, lane = t & 31, wid = t >> 5;
    const int qt = (int)(gridDim.x - 1) - (int)blockIdx.x;   // big tiles first
    const int bh = blockIdx.y;
    const int qbase = qt * 128;
    const size_t hb = (size_t)bh * TT * 64;
    const int warpQ = wid * 16;

    // Q copy
    #pragma unroll
    for (int i = 0; i < 4; ++i) {
        const int idx = t + i * 256;
        const int row = idx >> 3, seg = idx & 7;
        const uint32_t so = SMEM_SWIZZLE_128B((uint32_t)(row * 128 + seg * 16));
        cp16(sb + Q_O + so, qq + hb + (size_t)(qbase + row) * 64 + seg * 8);
    }
    auto load_kv = [&](int buf, int kt) {
        const uint32_t dst = sb + KV0 + buf * KV_STRIDE;
        #pragma unroll
        for (int i = 0; i < 2; ++i) {
            const int idx = t + i * 256;
            const int row = idx >> 3, seg = idx & 7;
            const uint32_t so = SMEM_SWIZZLE_128B((uint32_t)(row * 128 + seg * 16));
            const size_t g = hb + (size_t)(kt * 64 + row) * 64 + seg * 8;
            cp16(dst + K_O + so, kk + g);
            cp16(dst + V_O + so, vv + g);
        }
    };
    const int nkt = 2 * qt + 2;
    load_kv(0, 0);
    CP_COMMIT();
    load_kv(1, 1);
    CP_COMMIT();

    uint32_t qa[4][4];
    float o[8][4];
    #pragma unroll
    for (int j = 0; j < 8; ++j)
        #pragma unroll
        for (int e = 0; e < 4; ++e) o[j][e] = 0.f;
    float m0r = -1e30f, m1r = -1e30f, l0r = 0.f, l1r = 0.f;

    int buf = 0;
    for (int kt = 0; kt < nkt; ++kt) {
        if (kt == nkt - 1) { CP_WAIT0(); } else { CP_WAIT1(); }
        __syncthreads();
        if (kt + 2 < nkt) {
            int nb = buf + 2; if (nb >= 3) nb -= 3;
            load_kv(nb, kt + 2);
            CP_COMMIT();
        }

        if (kt == 0) {
            const uint32_t qrow = (uint32_t)(warpQ + (lane & 15));
            const uint32_t qbyt = (uint32_t)((lane >> 4) * 16);
            #pragma unroll
            for (int s = 0; s < 4; ++s)
                ldm_x4(qa[s], sb + Q_O + SMEM_SWIZZLE_128B(qrow * 128 + s * 32 + qbyt));
        }
        const uint32_t st = sb + KV0 + buf * KV_STRIDE;

        // ---- S = Q16 K16^T ----
        float sacc[8][4];
        #pragma unroll
        for (int j = 0; j < 8; ++j) { sacc[j][0]=0.f; sacc[j][1]=0.f; sacc[j][2]=0.f; sacc[j][3]=0.f; }
        #pragma unroll
        for (int j = 0; j < 8; ++j) {
            const uint32_t krow = (uint32_t)(j * 8 + (lane & 7));
            const uint32_t kbyt = (uint32_t)(((lane >> 3) & 3) * 16);
            uint32_t kb0[4], kb1[4];
            ldm_x4(kb0, st + K_O + SMEM_SWIZZLE_128B(krow * 128 + kbyt));
            ldm_x4(kb1, st + K_O + SMEM_SWIZZLE_128B(krow * 128 + 64 + kbyt));
            mma_f16(sacc[j], qa[0], kb0 + 0); mma_f16(sacc[j], qa[1], kb0 + 2);
            mma_f16(sacc[j], qa[2], kb1 + 0); mma_f16(sacc[j], qa[3], kb1 + 2);
        }

        // ---- causal mask (last two K-tiles only) ----
        if (kt >= 2 * qt) {
            const int r0 = qbase + warpQ + (lane >> 2);
            #pragma unroll
            for (int j = 0; j < 8; ++j) {
                const int c = kt * 64 + j * 8 + (lane & 3) * 2;
                if (c     > r0)     sacc[j][0] = -1e30f;
                if (c + 1 > r0)     sacc[j][1] = -1e30f;
                if (c     > r0 + 8) sacc[j][2] = -1e30f;
                if (c + 1 > r0 + 8) sacc[j][3] = -1e30f;
            }
        }

        // ---- online softmax (base-2) ----
        float tm0 = -1e30f, tm1 = -1e30f;
        #pragma unroll
        for (int j = 0; j < 8; ++j) {
            tm0 = fmaxf(tm0, fmaxf(sacc[j][0], sacc[j][1]));
            tm1 = fmaxf(tm1, fmaxf(sacc[j][2], sacc[j][3]));
        }
        tm0 = fmaxf(tm0, __shfl_xor_sync(0xffffffffu, tm0, 1));
        tm0 = fmaxf(tm0, __shfl_xor_sync(0xffffffffu, tm0, 2));
        tm1 = fmaxf(tm1, __shfl_xor_sync(0xffffffffu, tm1, 1));
        tm1 = fmaxf(tm1, __shfl_xor_sync(0xffffffffu, tm1, 2));
        const float mn0 = fmaxf(m0r, tm0), mn1 = fmaxf(m1r, tm1);
        const float al0 = exp2f(m0r - mn0), al1 = exp2f(m1r - mn1);
        m0r = mn0; m1r = mn1;
        float rs0 = 0.f, rs1 = 0.f;
        #pragma unroll
        for (int j = 0; j < 8; ++j) {
            sacc[j][0] = exp2f(sacc[j][0] - mn0);
            sacc[j][1] = exp2f(sacc[j][1] - mn0);
            sacc[j][2] = exp2f(sacc[j][2] - mn1);
            sacc[j][3] = exp2f(sacc[j][3] - mn1);
            rs0 += sacc[j][0] + sacc[j][1];
            rs1 += sacc[j][2] + sacc[j][3];
        }
        rs0 += __shfl_xor_sync(0xffffffffu, rs0, 1);
        rs0 += __shfl_xor_sync(0xffffffffu, rs0, 2);
        rs1 += __shfl_xor_sync(0xffffffffu, rs1, 1);
        rs1 += __shfl_xor_sync(0xffffffffu, rs1, 2);
        l0r = l0r * al0 + rs0;
        l1r = l1r * al1 + rs1;
        #pragma unroll
        for (int j = 0; j < 8; ++j) {
            o[j][0] *= al0; o[j][1] *= al0; o[j][2] *= al1; o[j][3] *= al1;
        }

        // ---- P -> fp16 A-operand fragments ----
        uint32_t pa[4][4];
        #pragma unroll
        for (int s = 0; s < 4; ++s) {
            pa[s][0] = packh2(__float2half_rn(sacc[2*s][0]),   __float2half_rn(sacc[2*s][1]));
            pa[s][1] = packh2(__float2half_rn(sacc[2*s][2]),   __float2half_rn(sacc[2*s][3]));
            pa[s][2] = packh2(__float2half_rn(sacc[2*s+1][0]), __float2half_rn(sacc[2*s+1][1]));
            pa[s][3] = packh2(__float2half_rn(sacc[2*s+1][2]), __float2half_rn(sacc[2*s+1][3]));
        }

        // ---- O += P16 V16 (V^T via ldmatrix.trans) ----
        #pragma unroll
        for (int jp = 0; jp < 4; ++jp) {
            #pragma unroll
            for (int s = 0; s < 4; ++s) {
                const uint32_t vrow = (uint32_t)(s * 16 + (lane & 15));
                const uint32_t vbyt = (uint32_t)(jp * 32 + (lane >> 4) * 16);
                uint32_t vb[4];
                ldm_x4_trans(vb, st + V_O + SMEM_SWIZZLE_128B(vrow * 128 + vbyt));
                mma_f16(o[2*jp],     pa[s], vb + 0);
                mma_f16(o[2*jp + 1], pa[s], vb + 2);
            }
        }
        ++buf; if (buf >= 3) buf -= 3;
    }

    // ---- epilogue: normalize, write y (single fp16) ----
    const float inv0 = 1.0f / l0r, inv1 = 1.0f / l1r;
    const int b = bh / HH, h = bh - b * HH;
    const size_t row0 = (size_t)b * TT + qbase + warpQ + (lane >> 2);
    #pragma unroll
    for (int j = 0; j < 8; ++j) {
        const int col = h * 64 + j * 8 + (lane & 3) * 2;
        *(uint32_t*)(yy + row0 * CC + col) =
            packh2(__float2half_rn(o[j][0] * inv0), __float2half_rn(o[j][1] * inv0));
        *(uint32_t*)(yy + (row0 + 8) * CC + col) =
            packh2(__float2half_rn(o[j][2] * inv1), __float2half_rn(o[j][3] * inv1));
    }
}

// ================= launch =================
extern "C" void kernel_launch(void* const* d_in, const int* in_sizes, int n_in,
                              void* d_out, int out_size)
{
    const float* x       = (const float*)d_in[0];
    const float* ln1_g   = (const float*)d_in[1];
    const float* ln1_b   = (const float*)d_in[2];
    const float* w_attn  = (const float*)d_in[3];
    const float* b_attn  = (const float*)d_in[4];
    const float* w_aproj = (const float*)d_in[5];
    const float* b_aproj = (const float*)d_in[6];
    const float* ln2_g   = (const float*)d_in[7];
    const float* ln2_b   = (const float*)d_in[8];
    const float* w_fc    = (const float*)d_in[9];
    const float* b_fc    = (const float*)d_in[10];
    const float* w_mproj = (const float*)d_in[11];
    const float* b_mproj = (const float*)d_in[12];
    float* out = (float*)d_out;

    __half *h1,*y,*h2,*fc,*wq,*wa,*wf,*wm,*qs,*ks,*vs;
    float *x1;
    cudaGetSymbolAddress((void**)&h1, g_h1);
    cudaGetSymbolAddress((void**)&y,  g_y);
    cudaGetSymbolAddress((void**)&x1, g_x1);
    cudaGetSymbolAddress((void**)&h2, g_h2);
    cudaGetSymbolAddress((void**)&fc, g_fc);
    cudaGetSymbolAddress((void**)&wq, g_wq);
    cudaGetSymbolAddress((void**)&wa, g_wa);
    cudaGetSymbolAddress((void**)&wf, g_wf);
    cudaGetSymbolAddress((void**)&wm, g_wm);
    cudaGetSymbolAddress((void**)&qs, g_qs);
    cudaGetSymbolAddress((void**)&ks, g_ks);
    cudaGetSymbolAddress((void**)&vs, g_vs);

    cudaFuncSetAttribute(hmma_gemm<1>, cudaFuncAttributeMaxDynamicSharedMemorySize, GEMM_SMEM);
    cudaFuncSetAttribute(hmma_gemm<2>, cudaFuncAttributeMaxDynamicSharedMemorySize, GEMM_SMEM);
    cudaFuncSetAttribute(hmma_gemm<3>, cudaFuncAttributeMaxDynamicSharedMemorySize, GEMM_SMEM);
    cudaFuncSetAttribute(attn_mma,     cudaFuncAttributeMaxDynamicSharedMemorySize, ATT_SMEM);

    // weight transpose
    tsplit_kernel<<<dim3(QKVC/32, CC/32),  dim3(256)>>>(w_attn,  wq, CC,  QKVC);
    tsplit_kernel<<<dim3(CC/32,   CC/32),  dim3(256)>>>(w_aproj, wa, CC,  CC);
    tsplit_kernel<<<dim3(FFC/32,  CC/32),  dim3(256)>>>(w_fc,    wf, CC,  FFC);
    tsplit_kernel<<<dim3(CC/32,   FFC/32), dim3(256)>>>(w_mproj, wm, FFC, CC);

    // 1) h1 = ln1(x)
    ln_h_kernel<<<NROWS/8, 256>>>(x, ln1_g, ln1_b, h1);
    // 2) q/k/v = per-head(h1 @ w_attn + b_attn), Q scaled
    hmma_gemm<3><<<dim3(QKVC/128, NROWS/128), 256, GEMM_SMEM>>>(
        h1, wq, b_attn, nullptr, nullptr, qs, ks, vs, NROWS, QKVC, CC);
    // 3) y = attention
    attn_mma<<<dim3(TT/128, BB*HH), 256, ATT_SMEM>>>(qs, ks, vs, y);
    // 4) x1 = y @ w_aproj + b_aproj + x
    hmma_gemm<2><<<dim3(CC/128, NROWS/128), 256, GEMM_SMEM>>>(
        y, wa, b_aproj, x, x1, nullptr, nullptr, nullptr, NROWS, CC, CC);
    // 5) h2 = ln2(x1)
    ln_h_kernel<<<NROWS/8, 256>>>(x1, ln2_g, ln2_b, h2);
    // 6) fc = gelu(h2 @ w_fc + b_fc)
    hmma_gemm<1><<<dim3(FFC/128, NROWS/128), 256, GEMM_SMEM>>>(
        h2, wf, b_fc, nullptr, nullptr, fc, nullptr, nullptr, NROWS, FFC, CC);
    // 7) out = fc @ w_mproj + b_mproj + x1
    hmma_gemm<2><<<dim3(CC/128, NROWS/128), 256, GEMM_SMEM>>>(
        fc, wm, b_mproj, x1, out, nullptr, nullptr, nullptr, NROWS, CC, FFC);
}